// round 11
// baseline (speedup 1.0000x reference)
#include <cuda_runtime.h>
#include <cuda_bf16.h>
#include <cstdint>
#include <math.h>

typedef __nv_bfloat16 bf16;

#define BQ 4
#define NQ 1024
#define CQ 1024
#define HQ 16
#define IQ 77
#define IDQ 768
#define HDQ 64
#define HIDQ 4096
#define SQ (IQ + NQ)   // 1101
#define SQP 1152       // padded KV length for transposed V

// ---------------- device scratch ----------------
// big-GEMM weights: tiled [NT=N/128][KC=K/64] blocks of 128x64 bf16 (16KB), SW128-swizzled
__device__ __align__(16) bf16 g_wqkv [3*CQ*CQ];
__device__ __align__(16) bf16 g_wproj[CQ*CQ];
__device__ __align__(16) bf16 g_wfc1 [2*HIDQ*CQ];   // [fc1 ; pfc1] stacked on N
__device__ __align__(16) bf16 g_wfc2 [CQ*2*HIDQ];   // [g2*fc2 | gate*pfc2] on K
__device__ __align__(16) bf16 g_wl1  [CQ*IDQ];
__device__ __align__(16) bf16 g_wl2  [CQ*CQ];

__device__ __align__(16) bf16 g_insln[BQ*IQ*IDQ];
__device__ __align__(16) bf16 g_hir  [BQ*IQ*CQ];
__device__ __align__(16) bf16 g_cat  [BQ*SQ*CQ];
__device__ __align__(16) bf16 g_qbuf [BQ*HQ*SQ*HDQ];
__device__ __align__(16) bf16 g_kbuf [BQ*HQ*SQ*HDQ];
__device__ __align__(16) bf16 g_vbuf [BQ*HQ*HDQ*SQP];   // TRANSPOSED [B,H,HD,SQP]
__device__ __align__(16) bf16 g_obuf [BQ*NQ*CQ];
__device__ __align__(16) bf16 g_ybuf [BQ*NQ*CQ];
__device__ __align__(16) bf16 g_h1   [BQ*NQ*2*HIDQ];
__device__ __align__(16) float g_x1  [BQ*NQ*CQ];
__device__ float g_qkvbias[3*CQ];
__device__ float g_fb1c[2*HIDQ];
__device__ float g_cb[CQ];

// ---------------- helpers ----------------
__device__ __forceinline__ uint32_t smem_u32(const void* p) {
    return (uint32_t)__cvta_generic_to_shared(p);
}
__device__ __forceinline__ void cpa16(uint32_t s, const void* g, bool p) {
    int sz = p ? 16 : 0;
    asm volatile("cp.async.cg.shared.global [%0], [%1], 16, %2;"
                 :: "r"(s), "l"(g), "r"(sz));
}
__device__ __forceinline__ void cp_commit() { asm volatile("cp.async.commit_group;"); }
template <int N_> __device__ __forceinline__ void cp_wait() {
    asm volatile("cp.async.wait_group %0;" :: "n"(N_));
}
__device__ __forceinline__ void ldm4(uint32_t* r, uint32_t a) {
    asm volatile("ldmatrix.sync.aligned.m8n8.x4.shared.b16 {%0,%1,%2,%3}, [%4];"
        : "=r"(r[0]), "=r"(r[1]), "=r"(r[2]), "=r"(r[3]) : "r"(a));
}
__device__ __forceinline__ void mma_bf16(float* d, const uint32_t* a, const uint32_t* b) {
    asm volatile("mma.sync.aligned.m16n8k16.row.col.f32.bf16.bf16.f32 "
        "{%0,%1,%2,%3}, {%4,%5,%6,%7}, {%8,%9}, {%0,%1,%2,%3};"
        : "+f"(d[0]), "+f"(d[1]), "+f"(d[2]), "+f"(d[3])
        : "r"(a[0]), "r"(a[1]), "r"(a[2]), "r"(a[3]), "r"(b[0]), "r"(b[1]));
}
__device__ __forceinline__ float gelu_exact(float x) {
    return 0.5f * x * (1.0f + erff(x * 0.70710678118654752f));
}
__device__ __forceinline__ uint32_t packbf(float a, float b) {
    __nv_bfloat162 t = __floats2bfloat162_rn(a, b);
    return *reinterpret_cast<uint32_t*>(&t);
}

// tiled weight addressing: element (n, k) of an [N][K] weight; 128x64 blocks, KC = K/64
__device__ __forceinline__ size_t wt_byteoff(int KC, int n, int k) {
    int nt = n >> 7, rl = n & 127, kc = k >> 6, cl = k & 63;
    size_t blk = ((size_t)(nt * KC + kc)) * 16384;
    uint32_t off = (uint32_t)(rl * 128 + cl * 2);
    uint32_t sw = off ^ ((off >> 3) & 0x70);
    return blk + sw;
}

#if defined(__CUDA_ARCH_FEAT_SM103_ALL)
#define HAS_TG 1
__device__ __forceinline__ uint32_t elect1() {
    uint32_t p;
    asm volatile("{\n\t.reg .pred p;\n\telect.sync _|p, 0xFFFFFFFF;\n\tselp.b32 %0, 1, 0, p;\n\t}"
        : "=r"(p));
    return p;
}
__device__ __forceinline__ void mbar_init(uint32_t a, uint32_t cnt) {
    asm volatile("mbarrier.init.shared.b64 [%0], %1;" :: "r"(a), "r"(cnt) : "memory");
}
__device__ __forceinline__ void mbar_wait(uint32_t a, int parity) {
    asm volatile("{\n\t.reg .pred P;\n\tWL%=:\n\t"
        "mbarrier.try_wait.parity.shared::cta.b64 P, [%0], %1;\n\t"
        "@!P bra WL%=;\n\t}" :: "r"(a), "r"(parity) : "memory");
}
__device__ __forceinline__ void mbar_expect_tx(uint32_t a, uint32_t bytes) {
    asm volatile("mbarrier.arrive.expect_tx.shared.b64 _, [%0], %1;"
        :: "r"(a), "r"(bytes) : "memory");
}
__device__ __forceinline__ void bulk_ld(uint32_t dst, const void* src, uint32_t bytes, uint32_t mbar) {
    asm volatile("cp.async.bulk.shared::cluster.global.mbarrier::complete_tx::bytes "
        "[%0], [%1], %2, [%3];"
        :: "r"(dst), "l"(src), "r"(bytes), "r"(mbar) : "memory");
}
__device__ __forceinline__ void tg_mma_f16_ss(uint32_t d, uint64_t ad, uint64_t bd,
                                              uint32_t idesc, bool en) {
    uint32_t e = en ? 1u : 0u;
    asm volatile("{\n\t.reg .pred p;\n\tsetp.ne.u32 p, %4, 0;\n\t"
        "tcgen05.mma.cta_group::1.kind::f16 [%0], %1, %2, %3, {%5,%5,%5,%5}, p;\n\t}"
        :: "r"(d), "l"(ad), "l"(bd), "r"(idesc), "r"(e), "r"(0u) : "memory");
}
__device__ __forceinline__ void tg_commit(uint32_t mbar) {
    asm volatile("tcgen05.commit.cta_group::1.mbarrier::arrive::one.shared::cluster.b64 [%0];"
        :: "r"(mbar) : "memory");
}
__device__ __forceinline__ void tg_ld32(uint32_t* r, uint32_t a) {
    asm volatile("tcgen05.ld.sync.aligned.32x32b.x32.b32 "
        "{%0,%1,%2,%3,%4,%5,%6,%7,%8,%9,%10,%11,%12,%13,%14,%15,"
        "%16,%17,%18,%19,%20,%21,%22,%23,%24,%25,%26,%27,%28,%29,%30,%31}, [%32];"
        : "=r"(r[0]),"=r"(r[1]),"=r"(r[2]),"=r"(r[3]),"=r"(r[4]),"=r"(r[5]),"=r"(r[6]),"=r"(r[7]),
          "=r"(r[8]),"=r"(r[9]),"=r"(r[10]),"=r"(r[11]),"=r"(r[12]),"=r"(r[13]),"=r"(r[14]),"=r"(r[15]),
          "=r"(r[16]),"=r"(r[17]),"=r"(r[18]),"=r"(r[19]),"=r"(r[20]),"=r"(r[21]),"=r"(r[22]),"=r"(r[23]),
          "=r"(r[24]),"=r"(r[25]),"=r"(r[26]),"=r"(r[27]),"=r"(r[28]),"=r"(r[29]),"=r"(r[30]),"=r"(r[31])
        : "r"(a));
}
#define TG_WAIT_LD()  asm volatile("tcgen05.wait::ld.sync.aligned;" ::: "memory")
#define TG_FENCE_AFTER() asm volatile("tcgen05.fence::after_thread_sync;" ::: "memory")
#define TG_ALLOC(sm, n) asm volatile("tcgen05.alloc.cta_group::1.sync.aligned.shared::cta.b32 [%0], %1;" :: "r"(sm), "r"((uint32_t)(n)) : "memory")
#define TG_DEALLOC(t, n) asm volatile("tcgen05.dealloc.cta_group::1.sync.aligned.b32 %0, %1;" :: "r"(t), "r"((uint32_t)(n)))
#define TG_RELINQ() asm volatile("tcgen05.relinquish_alloc_permit.cta_group::1.sync.aligned;")

static __device__ __forceinline__ uint64_t mk_desc(uint32_t addr) {
    return ((uint64_t)2 << 61) | ((uint64_t)1 << 46) | ((uint64_t)64 << 32) |
           ((uint64_t)1 << 16) | (uint64_t)((addr >> 4) & 0x3FFF);
}
#endif

// ---------------- fused front-end: tiled weight cvt + bias prep + LN(ins) + LN(x) ----
struct MegaArgs {
    const float *qkvw, *pw, *l1w, *l2w, *f1w, *p1w, *f2w, *p2w;
    const float *qb, *vb, *f1b, *p1b, *f2b, *p2b, *g2, *gate;
    bf16 *wqkv, *wproj, *wl1, *wl2, *wfc1, *wfc2;
    float *qkvbias, *fb1c, *cb;
    const float *ins, *ilw, *ilb, *x, *n1w, *n1b;
    bf16 *insln, *cat;
};

#define CVT_V4_BLOCKS 22272
#define CVT_MISC_BLOCKS 48
#define LNI_BLOCKS (BQ * IQ)     // 308
#define LNX_BLOCKS (BQ * NQ)     // 4096
#define MEGA_BLOCKS (CVT_V4_BLOCKS + CVT_MISC_BLOCKS + LNI_BLOCKS + LNX_BLOCKS)

__device__ __forceinline__ void cvt_plain(const float* src, bf16* dst, int i) {
    float4 v = *(const float4*)(src + (size_t)i * 4);
    uint2 o;
    o.x = packbf(v.x, v.y);
    o.y = packbf(v.z, v.w);
    *(uint2*)(dst + (size_t)i * 4) = o;
}

__device__ __forceinline__ void cvt_tiled4(const float* row, bf16* dst, int KC,
                                           int n, int k, float s) {
    float4 v = *(const float4*)(row + k);
    uint2 o;
    o.x = packbf(v.x * s, v.y * s);
    o.y = packbf(v.z * s, v.w * s);
    *(uint2*)((char*)dst + wt_byteoff(KC, n, k)) = o;
}

__device__ void ln_row(const float* __restrict__ p, const float* __restrict__ w,
                       const float* __restrict__ bia, bf16* __restrict__ op,
                       int D, float* sm) {
    int tid = threadIdx.x;
    float s = 0.0f, s2 = 0.0f;
    for (int i = tid; i < D; i += 256) { float v = p[i]; s += v; s2 += v * v; }
    #pragma unroll
    for (int o = 16; o; o >>= 1) {
        s  += __shfl_xor_sync(0xffffffffu, s, o);
        s2 += __shfl_xor_sync(0xffffffffu, s2, o);
    }
    int warp = tid >> 5, lane = tid & 31;
    if (lane == 0) { sm[warp] = s; sm[warp + 8] = s2; }
    __syncthreads();
    s = 0.0f; s2 = 0.0f;
    #pragma unroll
    for (int i = 0; i < 8; i++) { s += sm[i]; s2 += sm[i + 8]; }
    float m = s / D;
    float var = s2 / D - m * m;
    float inv = rsqrtf(var + 1e-5f);
    for (int i = tid; i < D; i += 256)
        op[i] = __float2bfloat16((p[i] - m) * inv * w[i] + bia[i]);
}

__global__ void mega_pre_kernel(MegaArgs a) {
    __shared__ float sm[16];
    int bid = blockIdx.x;
    int tid = threadIdx.x;
    if (bid < CVT_V4_BLOCKS) {
        int i = bid * 256 + tid;
        if (i < 786432) {                       // wqkv 3072x1024, KC=16
            int n = i >> 8, k = (i & 255) * 4;
            cvt_tiled4(a.qkvw + (size_t)n * CQ, a.wqkv, 16, n, k, 1.0f);
        } else if (i < 1048576) {               // wproj 1024x1024, KC=16
            int j = i - 786432;
            int n = j >> 8, k = (j & 255) * 4;
            cvt_tiled4(a.pw + (size_t)n * CQ, a.wproj, 16, n, k, 1.0f);
        } else if (i < 1245184) {               // wl1 1024x768, KC=12
            int j = i - 1048576;
            int n = j / 192, k = (j % 192) * 4;
            cvt_tiled4(a.l1w + (size_t)n * IDQ, a.wl1, 12, n, k, 1.0f);
        } else if (i < 1507328) {               // wl2 1024x1024, KC=16
            int j = i - 1245184;
            int n = j >> 8, k = (j & 255) * 4;
            cvt_tiled4(a.l2w + (size_t)n * CQ, a.wl2, 16, n, k, 1.0f);
        } else if (i < 2555904) {               // fc1 rows [0,4096), KC=16
            int j = i - 1507328;
            int n = j >> 8, k = (j & 255) * 4;
            cvt_tiled4(a.f1w + (size_t)n * CQ, a.wfc1, 16, n, k, 1.0f);
        } else if (i < 3604480) {               // pfc1 rows [4096,8192), KC=16
            int j = i - 2555904;
            int n = j >> 8, k = (j & 255) * 4;
            cvt_tiled4(a.p1w + (size_t)n * CQ, a.wfc1, 16, n + HIDQ, k, 1.0f);
        } else if (i < 4653056) {               // g2*fc2 cols [0,4096), KC=128
            int j = i - 3604480;
            int n = j >> 10, k = (j & 1023) * 4;
            float s = a.g2[n];
            float4 v = *(const float4*)(a.f2w + (size_t)n * HIDQ + k);
            uint2 o;
            o.x = packbf(v.x * s, v.y * s);
            o.y = packbf(v.z * s, v.w * s);
            *(uint2*)((char*)a.wfc2 + wt_byteoff(128, n, k)) = o;
        } else {                                // gate*pfc2 cols [4096,8192), KC=128
            int j = i - 4653056;
            int n = j >> 10, kk = (j & 1023) * 4;
            float s = a.gate[0];
            float4 v = *(const float4*)(a.p2w + (size_t)n * HIDQ + kk);
            uint2 o;
            o.x = packbf(v.x * s, v.y * s);
            o.y = packbf(v.z * s, v.w * s);
            *(uint2*)((char*)a.wfc2 + wt_byteoff(128, n, kk + HIDQ)) = o;
        }
    } else if (bid < CVT_V4_BLOCKS + CVT_MISC_BLOCKS) {
        int t = (bid - CVT_V4_BLOCKS) * 256 + tid;
        if (t < 3072) {
            float v = 0.0f;
            if (t < CQ) v = a.qb[t];
            else if (t >= 2 * CQ) v = a.vb[t - 2 * CQ];
            a.qkvbias[t] = v;
        } else if (t < 11264) {
            int j = t - 3072;
            a.fb1c[j] = (j < HIDQ) ? a.f1b[j] : a.p1b[j - HIDQ];
        } else {
            int j = t - 11264;
            a.cb[j] = a.g2[j] * a.f2b[j] + a.gate[0] * a.p2b[j];
        }
    } else if (bid < CVT_V4_BLOCKS + CVT_MISC_BLOCKS + LNI_BLOCKS) {
        int row = bid - (CVT_V4_BLOCKS + CVT_MISC_BLOCKS);
        ln_row(a.ins + (size_t)row * IDQ, a.ilw, a.ilb,
               a.insln + (size_t)row * IDQ, IDQ, sm);
    } else {
        int row = bid - (CVT_V4_BLOCKS + CVT_MISC_BLOCKS + LNI_BLOCKS);
        int bb = row >> 10, n = row & 1023;
        ln_row(a.x + (size_t)row * CQ, a.n1w, a.n1b,
               a.cat + (size_t)(bb * SQ + IQ + n) * CQ, CQ, sm);
    }
}

// ---------------- LayerNorm (standalone — LN2 only) ----------------
__global__ void ln_kernel(const float* __restrict__ in, const float* __restrict__ w,
                          const float* __restrict__ bia, bf16* __restrict__ out, int D) {
    __shared__ float sm[16];
    int row = blockIdx.x;
    ln_row(in + (size_t)row * D, w, bia, out + (size_t)row * D, D, sm);
}

// ---------------- epilogue params ----------------
struct EpiParams {
    const float* bias  = nullptr;
    bf16*  outb        = nullptr;
    float* outf        = nullptr;
    const float* resid = nullptr;
    const float* gvec  = nullptr;
    bf16* q = nullptr; bf16* k = nullptr; bf16* v = nullptr;
};

// ---------------- big GEMM: C[M,N] = A[M,K] @ W_tiled[N,K]^T ----------------
// 128x128 tile, BK=64, 3 stages. A via cp.async (1024 x 16B); B via ONE
// cp.async.bulk of a pre-swizzled 16KB block, completing on a per-stage mbarrier.
// MODE 0: outb = gelu(acc+bias), pitch N
// MODE 1: scatter into cat rows [0,I)
// MODE 2: qkv split; q scaled 0.125; v TRANSPOSED -> [B,H,HD,SQP]
// MODE 3: outf = resid + gvec[c]*(acc+bias), pitch CQ
// MODE 4: outf = resid + acc + bias[c], pitch CQ
#define BG_SMEM 100352

template <int MODE>
__global__ __launch_bounds__(256, 2)
void big_gemm_kernel(const bf16* __restrict__ A, const bf16* __restrict__ W,
                     int M, int N, int K, EpiParams ep) {
#if defined(__CUDA_ARCH_FEAT_SM103_ALL)
    extern __shared__ char dsm[];
    char* base = (char*)(((uintptr_t)dsm + 1023) & ~(uintptr_t)1023);
    const uint32_t sb = smem_u32(base);
    const int tid = threadIdx.x, warp = tid >> 5;
    const int mbase = blockIdx.y * 128, nbase = blockIdx.x * 128;
    const int KC = K >> 6;

    if (warp == 0) { TG_ALLOC(sb, 128); }
    if (tid == 0) {
        mbar_init(sb + 8, 1);    // stage-done 0..2
        mbar_init(sb + 16, 1);
        mbar_init(sb + 24, 1);
        mbar_init(sb + 32, 1);   // B-full 0..2
        mbar_init(sb + 40, 1);
        mbar_init(sb + 48, 1);
    }
    __syncthreads();
    uint32_t tmem;
    asm volatile("ld.shared.b32 %0, [%1];" : "=r"(tmem) : "r"(sb));
    if (warp == 0) TG_RELINQ();

    const int NK = KC;
    int ph[3] = {0, 0, 0};
    int phf[3] = {0, 0, 0};

    auto stA = [&](int s) -> uint32_t { return sb + 2048 + s * 32768; };

    auto load_chunk = [&](int kt) {
        int s = kt % 3;
        int k0 = kt << 6;
        uint32_t a0 = stA(s);
        #pragma unroll
        for (int i = 0; i < 4; i++) {
            int idx = tid + i * 256;
            int r = idx >> 3, cch = idx & 7;
            uint32_t off = (uint32_t)(r * 128 + cch * 16);
            uint32_t sw = off ^ ((off >> 3) & 0x70);
            bool pa = (mbase + r) < M;
            const bf16* ga = pa ? (A + (size_t)(mbase + r) * K + k0 + cch * 8) : A;
            cpa16(a0 + sw, ga, pa);
        }
        cp_commit();
        if (tid == 0) {
            uint32_t mb = sb + 32 + 8 * s;
            mbar_expect_tx(mb, 16384);
            bulk_ld(a0 + 16384,
                    (const char*)W + ((size_t)(blockIdx.x * KC + kt)) * 16384,
                    16384, mb);
        }
    };

    const uint32_t lead = (warp == 0) ? elect1() : 0;
    const uint32_t idesc = (1u << 4) | (1u << 7) | (1u << 10) | (16u << 17) | (8u << 24);

    load_chunk(0);
    load_chunk(1);

    for (int kt = 0; kt < NK; kt++) {
        int s = kt % 3;
        if (kt + 1 < NK) cp_wait<1>(); else cp_wait<0>();
        asm volatile("fence.proxy.async.shared::cta;" ::: "memory");
        mbar_wait(sb + 32 + 8 * s, phf[s]);
        phf[s] ^= 1;
        __syncthreads();

        if (warp == 0 && lead) {
            uint64_t ad = mk_desc(stA(s));
            uint64_t bd = mk_desc(stA(s) + 16384);
            #pragma unroll
            for (int stp = 0; stp < 4; stp++)
                tg_mma_f16_ss(tmem, ad + stp * 2, bd + stp * 2, idesc, (kt > 0) || (stp > 0));
            tg_commit(sb + 8 + 8 * s);
        }

        if (kt + 2 < NK) {
            int s2 = (kt + 2) % 3;
            if (kt >= 1) { mbar_wait(sb + 8 + 8 * s2, ph[s2]); ph[s2] ^= 1; }
            load_chunk(kt + 2);
        }
    }

    { int s = (NK - 1) % 3; mbar_wait(sb + 8 + 8 * s, ph[s]); }
    TG_FENCE_AFTER();
    __syncthreads();

    if (tid < 128) {
        const int grow = mbase + tid;
        #pragma unroll
        for (int cc = 0; cc < 4; cc++) {
            uint32_t regs[32];
            tg_ld32(regs, tmem + cc * 32);
            TG_WAIT_LD();
            if (grow < M) {
                const int c0 = nbase + cc * 32;
                float vals[32];
                #pragma unroll
                for (int c = 0; c < 32; c++)
                    vals[c] = __uint_as_float(regs[c]) + ep.bias[c0 + c];

                if (MODE == 0) {
                    uint32_t pk[16];
                    #pragma unroll
                    for (int c = 0; c < 16; c++)
                        pk[c] = packbf(gelu_exact(vals[2*c]), gelu_exact(vals[2*c+1]));
                    uint4* dst = (uint4*)(ep.outb + (size_t)grow * N + c0);
                    #pragma unroll
                    for (int q = 0; q < 4; q++)
                        dst[q] = make_uint4(pk[4*q], pk[4*q+1], pk[4*q+2], pk[4*q+3]);
                } else if (MODE == 1) {
                    int bb = grow / IQ, ii = grow % IQ;
                    uint32_t pk[16];
                    #pragma unroll
                    for (int c = 0; c < 16; c++)
                        pk[c] = packbf(vals[2*c], vals[2*c+1]);
                    uint4* dst = (uint4*)(ep.outb + (size_t)(bb * SQ + ii) * CQ + c0);
                    #pragma unroll
                    for (int q = 0; q < 4; q++)
                        dst[q] = make_uint4(pk[4*q], pk[4*q+1], pk[4*q+2], pk[4*q+3]);
                } else if (MODE == 2) {
                    int bb = grow / SQ, s = grow % SQ;
                    int sec = c0 >> 10, hh = (c0 & 1023) >> 6, d0 = c0 & 63;
                    if (sec == 2) {
                        bf16* vt = ep.v + (size_t)(bb * HQ + hh) * HDQ * SQP;
                        #pragma unroll
                        for (int c = 0; c < 32; c++)
                            vt[(size_t)(d0 + c) * SQP + s] = __float2bfloat16(vals[c]);
                    } else {
                        size_t off = ((size_t)(bb * HQ + hh) * SQ + s) * HDQ + d0;
                        bf16* dstp; float scl = 1.0f;
                        if (sec == 0) { dstp = ep.q + off; scl = 0.125f; }
                        else          { dstp = ep.k + off; }
                        uint32_t pk[16];
                        #pragma unroll
                        for (int c = 0; c < 16; c++)
                            pk[c] = packbf(vals[2*c] * scl, vals[2*c+1] * scl);
                        uint4* dst = (uint4*)dstp;
                        #pragma unroll
                        for (int q = 0; q < 4; q++)
                            dst[q] = make_uint4(pk[4*q], pk[4*q+1], pk[4*q+2], pk[4*q+3]);
                    }
                } else if (MODE == 3) {
                    const float4* rs = (const float4*)(ep.resid + (size_t)grow * CQ + c0);
                    float4* dst = (float4*)(ep.outf + (size_t)grow * CQ + c0);
                    #pragma unroll
                    for (int q = 0; q < 8; q++) {
                        float4 rv = rs[q];
                        float4 o;
                        o.x = rv.x + ep.gvec[c0 + 4*q + 0] * vals[4*q + 0];
                        o.y = rv.y + ep.gvec[c0 + 4*q + 1] * vals[4*q + 1];
                        o.z = rv.z + ep.gvec[c0 + 4*q + 2] * vals[4*q + 2];
                        o.w = rv.w + ep.gvec[c0 + 4*q + 3] * vals[4*q + 3];
                        dst[q] = o;
                    }
                } else {
                    const float4* rs = (const float4*)(ep.resid + (size_t)grow * CQ + c0);
                    float4* dst = (float4*)(ep.outf + (size_t)grow * CQ + c0);
                    #pragma unroll
                    for (int q = 0; q < 8; q++) {
                        float4 rv = rs[q];
                        float4 o;
                        o.x = rv.x + vals[4*q + 0];
                        o.y = rv.y + vals[4*q + 1];
                        o.z = rv.z + vals[4*q + 2];
                        o.w = rv.w + vals[4*q + 3];
                        dst[q] = o;
                    }
                }
            }
        }
    }
    __syncthreads();
    if (warp == 0) TG_DEALLOC(tmem, 128);
#else
    // ======== mma.sync fallback (tiled B addressing) ========
    extern __shared__ bf16 smem[];
    bf16* sA = smem;
    bf16* sB = smem + 3 * 5120;
    const int tid  = threadIdx.x;
    const int lane = tid & 31, warp = tid >> 5;
    const int wm = warp & 1, wn = warp >> 1;
    const int mbase = blockIdx.y * 128, nbase = blockIdx.x * 128;
    const int KC = K >> 6;
    const int lr = tid >> 2, lc = (tid & 3) * 8;

    float acc[4][4][4];
    #pragma unroll
    for (int a = 0; a < 4; a++)
        #pragma unroll
        for (int b = 0; b < 4; b++)
            #pragma unroll
            for (int c = 0; c < 4; c++) acc[a][b][c] = 0.0f;

    const int NK = K >> 5;

    auto baddr = [&](int n, int k) -> const bf16* {
        return (const bf16*)((const char*)W + wt_byteoff(KC, n, k));
    };
    auto issue = [&](int kt) {
        int k0 = kt << 5;
        int st = kt % 3;
        bf16* dA = sA + st * 5120;
        bf16* dB = sB + st * 5120;
        bool p1 = (mbase + lr) < M;
        bool p2 = (mbase + lr + 64) < M;
        const bf16* ga1 = p1 ? (A + (size_t)(mbase + lr) * K + k0 + lc) : A;
        const bf16* ga2 = p2 ? (A + (size_t)(mbase + lr + 64) * K + k0 + lc) : A;
        cpa16(smem_u32(dA + lr * 40 + lc), ga1, p1);
        cpa16(smem_u32(dA + (lr + 64) * 40 + lc), ga2, p2);
        cpa16(smem_u32(dB + lr * 40 + lc), baddr(nbase + lr, k0 + lc), true);
        cpa16(smem_u32(dB + (lr + 64) * 40 + lc), baddr(nbase + lr + 64, k0 + lc), true);
    };

    issue(0); cp_commit();
    issue(1); cp_commit();

    for (int kt = 0; kt < NK; kt++) {
        if (kt + 1 < NK) cp_wait<1>(); else cp_wait<0>();
        __syncthreads();
        if (kt + 2 < NK) issue(kt + 2);
        cp_commit();

        const int st = kt % 3;
        const uint32_t a0 = smem_u32(sA + st * 5120);
        const uint32_t b0 = smem_u32(sB + st * 5120);
        #pragma unroll
        for (int ks = 0; ks < 2; ks++) {
            int kc = ks * 16;
            uint32_t af[4][4];
            #pragma unroll
            for (int im = 0; im < 4; im++) {
                int row = wm * 64 + im * 16 + (lane & 15);
                int col = kc + ((lane >> 4) << 3);
                ldm4(af[im], a0 + (uint32_t)((row * 40 + col) * 2));
            }
            uint32_t bfr[4][2];
            #pragma unroll
            for (int ib = 0; ib < 2; ib++) {
                int g = lane >> 3;
                int row = wn * 32 + ib * 16 + ((g >> 1) << 3) + (lane & 7);
                int col = kc + ((g & 1) << 3);
                uint32_t r4[4];
                ldm4(r4, b0 + (uint32_t)((row * 40 + col) * 2));
                bfr[2*ib][0] = r4[0]; bfr[2*ib][1] = r4[1];
                bfr[2*ib+1][0] = r4[2]; bfr[2*ib+1][1] = r4[3];
            }
            #pragma unroll
            for (int im = 0; im < 4; im++)
                #pragma unroll
                for (int in_ = 0; in_ < 4; in_++)
                    mma_bf16(acc[im][in_], af[im], bfr[in_]);
        }
    }

    #pragma unroll
    for (int im = 0; im < 4; im++)
        #pragma unroll
        for (int in_ = 0; in_ < 4; in_++)
            #pragma unroll
            for (int j = 0; j < 4; j++) {
                int r = mbase + wm * 64 + im * 16 + (lane >> 2) + ((j >> 1) << 3);
                int c = nbase + wn * 32 + in_ * 8 + ((lane & 3) << 1) + (j & 1);
                if (r >= M) continue;
                float v = acc[im][in_][j] + ep.bias[c];
                if (MODE == 0) {
                    ep.outb[(size_t)r * N + c] = __float2bfloat16(gelu_exact(v));
                } else if (MODE == 1) {
                    int bb = r / IQ, ii = r % IQ;
                    ep.outb[(size_t)(bb * SQ + ii) * CQ + c] = __float2bfloat16(v);
                } else if (MODE == 2) {
                    int bb = r / SQ, s = r % SQ;
                    int sec = c >> 10, hh = (c & 1023) >> 6, d = c & 63;
                    if (sec == 2) {
                        ep.v[((size_t)(bb * HQ + hh) * HDQ + d) * SQP + s] = __float2bfloat16(v);
                    } else {
                        size_t dst = ((size_t)(bb * HQ + hh) * SQ + s) * HDQ + d;
                        if (sec == 0) ep.q[dst] = __float2bfloat16(v * 0.125f);
                        else          ep.k[dst] = __float2bfloat16(v);
                    }
                } else if (MODE == 3) {
                    ep.outf[(size_t)r * CQ + c] = ep.resid[(size_t)r * CQ + c] + ep.gvec[c] * v;
                } else if (MODE == 4) {
                    ep.outf[(size_t)r * CQ + c] = ep.resid[(size_t)r * CQ + c] + v;
                }
            }
#endif
}

// ---------------- flash attention (round-8 tcgen05 version) ----------------
#define NCH ((SQ + 63) / 64)   // 18
#define FL_SMEM 84992

__global__ __launch_bounds__(128, 2)
void flash_kernel(const bf16* __restrict__ Q, const bf16* __restrict__ K,
                  const bf16* __restrict__ Vt, bf16* __restrict__ O) {
#if defined(__CUDA_ARCH_FEAT_SM103_ALL)
    extern __shared__ char dsm[];
    char* base = (char*)(((uintptr_t)dsm + 1023) & ~(uintptr_t)1023);
    const uint32_t sb = smem_u32(base);
    const int tid = threadIdx.x, warp = tid >> 5;
    const int q0 = blockIdx.x * 128;
    const int h = blockIdx.y, b = blockIdx.z;
    const char* qbase = (const char*)(Q + ((size_t)(b * HQ + h) * SQ + IQ + q0) * HDQ);
    const char* kbase = (const char*)(K + (size_t)(b * HQ + h) * SQ * HDQ);
    const char* vtbase = (const char*)(Vt + (size_t)(b * HQ + h) * HDQ * SQP);

    if (warp == 0) TG_ALLOC(sb, 128);
    if (tid == 0) { mbar_init(sb + 8, 1); mbar_init(sb + 16, 1); }
    __syncthreads();
    uint32_t tmem;
    asm volatile("ld.shared.b32 %0, [%1];" : "=r"(tmem) : "r"(sb));
    if (warp == 0) TG_RELINQ();

    const uint32_t sQ = sb + 1024;
    const uint32_t sP = sQ + 16384;
    const uint32_t sK = sP + 16384;
    const uint32_t sV = sK + 24576;

    #pragma unroll
    for (int i = 0; i < 8; i++) {
        int idx = tid + i * 128;
        int r = idx >> 3, cb = (idx & 7) * 16;
        uint32_t off = (uint32_t)(r * 128 + cb);
        uint32_t sw = off ^ ((off >> 3) & 0x70);
        *(uint4*)(base + 1024 + sw) = *(const uint4*)(qbase + (size_t)r * 128 + cb);
    }
    asm volatile("fence.proxy.async.shared::cta;" ::: "memory");

    auto issueKV = [&](int ci) {
        int st = ci % 3;
        int s0 = ci * 64;
        #pragma unroll
        for (int i = 0; i < 4; i++) {
            int idx = tid + i * 128;
            int r = idx >> 3, cb = (idx & 7) * 16;
            uint32_t off = (uint32_t)(r * 128 + cb);
            uint32_t sw = off ^ ((off >> 3) & 0x70);
            bool pk = (s0 + r) < SQ;
            const char* gk = pk ? (kbase + (size_t)(s0 + r) * 128 + cb) : kbase;
            cpa16(sK + st * 8192 + sw, gk, pk);
            const char* gv = vtbase + (size_t)r * (SQP * 2) + (size_t)s0 * 2 + cb;
            cpa16(sV + st * 8192 + sw, gv, true);
        }
        cp_commit();
    };

    const uint32_t lead = (warp == 0) ? elect1() : 0;
    const uint32_t idesc = (1u << 4) | (1u << 7) | (1u << 10) | (8u << 17) | (8u << 24);

    issueKV(0);
    issueKV(1);

    float rsum = 0.0f;
    const uint64_t qd = mk_desc(sQ);
    const uint64_t pd = mk_desc(sP);

    for (int ci = 0; ci < NCH; ci++) {
        int st = ci % 3;
        int s0 = ci * 64;
        if (ci + 1 < NCH) cp_wait<1>(); else cp_wait<0>();
        __syncthreads();

        if (warp == 0 && lead) {
            uint64_t kd = mk_desc(sK + st * 8192);
            #pragma unroll
            for (int stp = 0; stp < 4; stp++)
                tg_mma_f16_ss(tmem, qd + stp * 2, kd + stp * 2, idesc, stp > 0);
            tg_commit(sb + 8);
        }
        mbar_wait(sb + 8, ci & 1);
        TG_FENCE_AFTER();

        if (ci + 2 < NCH) issueKV(ci + 2);

        uint32_t sr[32], sr2[32];
        tg_ld32(sr, tmem);
        tg_ld32(sr2, tmem + 32);
        TG_WAIT_LD();
        uint32_t pk[32];
        #pragma unroll
        for (int j = 0; j < 16; j++) {
            float e0 = (s0 + 2*j     < SQ) ? __expf(__uint_as_float(sr[2*j]))     : 0.0f;
            float e1 = (s0 + 2*j + 1 < SQ) ? __expf(__uint_as_float(sr[2*j + 1])) : 0.0f;
            rsum += e0 + e1;
            pk[j] = packbf(e0, e1);
        }
        #pragma unroll
        for (int j = 0; j < 16; j++) {
            float e0 = (s0 + 32 + 2*j     < SQ) ? __expf(__uint_as_float(sr2[2*j]))     : 0.0f;
            float e1 = (s0 + 32 + 2*j + 1 < SQ) ? __expf(__uint_as_float(sr2[2*j + 1])) : 0.0f;
            rsum += e0 + e1;
            pk[16 + j] = packbf(e0, e1);
        }
        #pragma unroll
        for (int cbk = 0; cbk < 8; cbk++) {
            uint32_t off = (uint32_t)(tid * 128 + cbk * 16);
            uint32_t sw = off ^ ((off >> 3) & 0x70);
            *(uint4*)(base + (sP - sb) + sw) =
                make_uint4(pk[4*cbk], pk[4*cbk+1], pk[4*cbk+2], pk[4*cbk+3]);
        }
        asm volatile("fence.proxy.async.shared::cta;" ::: "memory");
        __syncthreads();

        if (warp == 0 && lead) {
            uint64_t vd = mk_desc(sV + st * 8192);
            #pragma unroll
            for (int stp = 0; stp < 4; stp++)
                tg_mma_f16_ss(tmem + 64, pd + stp * 2, vd + stp * 2, idesc,
                              (ci > 0) || (stp > 0));
            if (ci == NCH - 1) tg_commit(sb + 16);
        }
    }

    mbar_wait(sb + 16, 0);
    TG_FENCE_AFTER();

    uint32_t orr[32], orr2[32];
    tg_ld32(orr, tmem + 64);
    tg_ld32(orr2, tmem + 96);
    TG_WAIT_LD();
    float inv = 1.0f / rsum;
    uint32_t po[32];
    #pragma unroll
    for (int j = 0; j < 16; j++)
        po[j] = packbf(__uint_as_float(orr[2*j]) * inv, __uint_as_float(orr[2*j+1]) * inv);
    #pragma unroll
    for (int j = 0; j < 16; j++)
        po[16+j] = packbf(__uint_as_float(orr2[2*j]) * inv, __uint_as_float(orr2[2*j+1]) * inv);
    uint4* orow = (uint4*)(O + (size_t)(b * NQ + q0 + tid) * CQ + h * HDQ);
    #pragma unroll
    for (int q = 0; q < 8; q++)
        orow[q] = make_uint4(po[4*q], po[4*q+1], po[4*q+2], po[4*q+3]);

    __syncthreads();
    if (warp == 0) TG_DEALLOC(tmem, 128);
#else
    // ---- mma.sync fallback: two sequential 64-row subtiles, V from Vt ----
    extern __shared__ bf16 fsm[];
    bf16* sQs = fsm;
    bf16* sKb = fsm + 4608;
    bf16* sVb = sKb + 3 * 4608;
    const int tid = threadIdx.x, lane = tid & 31, warp = tid >> 5;
    const int h = blockIdx.y, b = blockIdx.z;
    const bf16* kbase = K + (size_t)(b * HQ + h) * SQ * HDQ;
    const bf16* vtbase = Vt + (size_t)(b * HQ + h) * HDQ * SQP;

    for (int sub = 0; sub < 2; sub++) {
        const int q0 = blockIdx.x * 128 + sub * 64;
        const bf16* qbase = Q + ((size_t)(b * HQ + h) * SQ + IQ + q0) * HDQ;

        #pragma unroll
        for (int i = 0; i < 4; i++) {
            int chunk = tid + i * 128;
            int r = chunk >> 3, c = (chunk & 7) * 8;
            *(uint4*)(sQs + r * 72 + c) = *(const uint4*)(qbase + (size_t)r * HDQ + c);
        }

        auto issueKV = [&](int ci) {
            int s0 = ci * 64;
            int bs = ci % 3;
            #pragma unroll
            for (int i = 0; i < 4; i++) {
                int chunk = tid + i * 128;
                int r = chunk >> 3, c = (chunk & 7) * 8;
                bool p = (s0 + r) < SQ;
                const bf16* gk = p ? (kbase + (size_t)(s0 + r) * HDQ + c) : kbase;
                cpa16(smem_u32(sKb + bs * 4608 + r * 72 + c), gk, p);
                const bf16* gv = vtbase + (size_t)r * SQP + s0 + c;
                cpa16(smem_u32(sVb + bs * 4608 + r * 72 + c), gv, true);
            }
        };

        float oacc[8][4];
        #pragma unroll
        for (int t = 0; t < 8; t++)
            #pragma unroll
            for (int j = 0; j < 4; j++) oacc[t][j] = 0.0f;
        float rmax[2] = {-1e30f, -1e30f}, rsum[2] = {0.0f, 0.0f};

        const uint32_t sQ0 = smem_u32(sQs);

        issueKV(0); cp_commit();
        issueKV(1); cp_commit();

        for (int ci = 0; ci < NCH; ci++) {
            int s0 = ci * 64;
            if (ci + 1 < NCH) cp_wait<1>(); else cp_wait<0>();
            __syncthreads();
            if (ci + 2 < NCH) issueKV(ci + 2);
            cp_commit();

            const uint32_t sK0 = smem_u32(sKb + (ci % 3) * 4608);
            const uint32_t sV0 = smem_u32(sVb + (ci % 3) * 4608);

            float sc[8][4];
            #pragma unroll
            for (int t = 0; t < 8; t++)
                #pragma unroll
                for (int j = 0; j < 4; j++) sc[t][j] = 0.0f;

            #pragma unroll
            for (int kk = 0; kk < 4; kk++) {
                uint32_t af[4];
                {
                    int row = warp * 16 + (lane & 15);
                    int col = kk * 16 + ((lane >> 4) << 3);
                    ldm4(af, sQ0 + (uint32_t)((row * 72 + col) * 2));
                }
                #pragma unroll
                for (int ib = 0; ib < 4; ib++) {
                    uint32_t r4[4];
                    int g = lane >> 3;
                    int row = ib * 16 + ((g >> 1) << 3) + (lane & 7);
                    int col = kk * 16 + ((g & 1) << 3);
                    ldm4(r4, sK0 + (uint32_t)((row * 72 + col) * 2));
                    uint32_t b0[2] = {r4[0], r4[1]}, b1[2] = {r4[2], r4[3]};
                    mma_bf16(sc[2 * ib], af, b0);
                    mma_bf16(sc[2 * ib + 1], af, b1);
                }
            }

            float cmax[2] = {-1e30f, -1e30f};
            #pragma unroll
            for (int t = 0; t < 8; t++)
                #pragma unroll
                for (int j = 0; j < 4; j++) {
                    int col = s0 + t * 8 + ((lane & 3) << 1) + (j & 1);
                    if (col >= SQ) sc[t][j] = -1e30f;
                    int rr = j >> 1;
                    cmax[rr] = fmaxf(cmax[rr], sc[t][j]);
                }
            #pragma unroll
            for (int rr = 0; rr < 2; rr++) {
                cmax[rr] = fmaxf(cmax[rr], __shfl_xor_sync(0xffffffffu, cmax[rr], 1));
                cmax[rr] = fmaxf(cmax[rr], __shfl_xor_sync(0xffffffffu, cmax[rr], 2));
            }
            float corr[2];
            #pragma unroll
            for (int rr = 0; rr < 2; rr++) {
                float nm = fmaxf(rmax[rr], cmax[rr]);
                corr[rr] = __expf(rmax[rr] - nm);
                rmax[rr] = nm;
            }
            float psum[2] = {0.0f, 0.0f};
            #pragma unroll
            for (int t = 0; t < 8; t++)
                #pragma unroll
                for (int j = 0; j < 4; j++) {
                    int rr = j >> 1;
                    float p = __expf(sc[t][j] - rmax[rr]);
                    sc[t][j] = p;
                    psum[rr] += p;
                }
            #pragma unroll
            for (int rr = 0; rr < 2; rr++) {
                psum[rr] += __shfl_xor_sync(0xffffffffu, psum[rr], 1);
                psum[rr] += __shfl_xor_sync(0xffffffffu, psum[rr], 2);
                rsum[rr] = rsum[rr] * corr[rr] + psum[rr];
            }
            #pragma unroll
            for (int t = 0; t < 8; t++)
                #pragma unroll
                for (int j = 0; j < 4; j++) oacc[t][j] *= corr[j >> 1];

            #pragma unroll
            for (int kk = 0; kk < 4; kk++) {
                uint32_t ap[4];
                ap[0] = packbf(sc[2 * kk][0], sc[2 * kk][1]);
                ap[1] = packbf(sc[2 * kk][2], sc[2 * kk][3]);
                ap[2] = packbf(sc[2 * kk + 1][0], sc[2 * kk + 1][1]);
                ap[3] = packbf(sc[2 * kk + 1][2], sc[2 * kk + 1][3]);
                #pragma unroll
                for (int ib = 0; ib < 4; ib++) {
                    uint32_t r4[4];
                    int g = lane >> 3;
                    int row = ib * 16 + ((g >> 1) << 3) + (lane & 7);
                    int col = kk * 16 + ((g & 1) << 3);
                    ldm4(r4, sV0 + (uint32_t)((row * 72 + col) * 2));
                    uint32_t b0[2] = {r4[0], r4[1]}, b1[2] = {r4[2], r4[3]};
                    mma_bf16(oacc[2 * ib], ap, b0);
                    mma_bf16(oacc[2 * ib + 1], ap, b1);
                }
            }
        }

        #pragma unroll
        for (int t = 0; t < 8; t++)
            #pragma unroll
            for (int j = 0; j < 4; j++) {
                int r = q0 + warp * 16 + (lane >> 2) + ((j >> 1) << 3);
                int c = h * HDQ + t * 8 + ((lane & 3) << 1) + (j & 1);
                O[(size_t)(b * NQ + r) * CQ + c] = __float2bfloat16(oacc[t][j] / rsum[j >> 1]);
            }
        __syncthreads();
    }
#endif
}

// ---------------- launch ----------------
extern "C" void kernel_launch(void* const* d_in, const int* in_sizes, int n_in,
                              void* d_out, int out_size) {
    const float* x    = (const float*)d_in[0];
    const float* ins  = (const float*)d_in[1];
    const float* n1w  = (const float*)d_in[2];
    const float* n1b  = (const float*)d_in[3];
    const float* qkvw = (const float*)d_in[4];
    const float* qb   = (const float*)d_in[5];
    const float* vb   = (const float*)d_in[6];
    const float* pw   = (const float*)d_in[7];
    const float* pb   = (const float*)d_in[8];
    const float* g1   = (const float*)d_in[9];
    const float* g2   = (const float*)d_in[10];
    const float* n2w  = (const float*)d_in[11];
    const float* n2b  = (const float*)d_in[12];
    const float* f1w  = (const float*)d_in[13];
    const float* f1b  = (const float*)d_in[14];
    const float* f2w  = (const float*)d_in[15];
    const float* f2bv = (const float*)d_in[16];
    const float* p1w  = (const float*)d_in[17];
    const float* p1b  = (const float*)d_in[18];
    const float* p2w  = (const float*)d_in[19];
    const float* p2b  = (const float*)d_in[20];
    const float* gate = (const float*)d_in[21];
    const float* ilw  = (const float*)d_in[22];
    const float* ilb  = (const float*)d_in[23];
    const float* l1w  = (const float*)d_in[24];
    const float* l1b  = (const float*)d_in[25];
    const float* l2w  = (const float*)d_in[26];
    const float* l2b  = (const float*)d_in[27];
    float* out = (float*)d_out;

    bf16 *w_qkv, *w_proj, *w_fc1, *w_fc2, *w_l1, *w_l2;
    bf16 *insln, *hir, *cat, *qB, *kB, *vB, *obuf, *ybuf, *h1;
    float *x1, *qkvbias, *fb1c, *cb;
    cudaGetSymbolAddress((void**)&w_qkv,  g_wqkv);
    cudaGetSymbolAddress((void**)&w_proj, g_wproj);
    cudaGetSymbolAddress((void**)&w_fc1,  g_wfc1);
    cudaGetSymbolAddress((void**)&w_fc2,  g_wfc2);
    cudaGetSymbolAddress((void**)&w_l1,   g_wl1);
    cudaGetSymbolAddress((void**)&w_l2,   g_wl2);
    cudaGetSymbolAddress((void**)&insln,  g_insln);
    cudaGetSymbolAddress((void**)&hir,    g_hir);
    cudaGetSymbolAddress((void**)&cat,    g_cat);
    cudaGetSymbolAddress((void**)&qB,     g_qbuf);
    cudaGetSymbolAddress((void**)&kB,     g_kbuf);
    cudaGetSymbolAddress((void**)&vB,     g_vbuf);
    cudaGetSymbolAddress((void**)&obuf,   g_obuf);
    cudaGetSymbolAddress((void**)&ybuf,   g_ybuf);
    cudaGetSymbolAddress((void**)&h1,     g_h1);
    cudaGetSymbolAddress((void**)&x1,     g_x1);
    cudaGetSymbolAddress((void**)&qkvbias, g_qkvbias);
    cudaGetSymbolAddress((void**)&fb1c,   g_fb1c);
    cudaGetSymbolAddress((void**)&cb,     g_cb);

    cudaFuncSetAttribute(big_gemm_kernel<0>, cudaFuncAttributeMaxDynamicSharedMemorySize, BG_SMEM);
    cudaFuncSetAttribute(big_gemm_kernel<1>, cudaFuncAttributeMaxDynamicSharedMemorySize, BG_SMEM);
    cudaFuncSetAttribute(big_gemm_kernel<2>, cudaFuncAttributeMaxDynamicSharedMemorySize, BG_SMEM);
    cudaFuncSetAttribute(big_gemm_kernel<3>, cudaFuncAttributeMaxDynamicSharedMemorySize, BG_SMEM);
    cudaFuncSetAttribute(big_gemm_kernel<4>, cudaFuncAttributeMaxDynamicSharedMemorySize, BG_SMEM);
    cudaFuncSetAttribute(flash_kernel, cudaFuncAttributeMaxDynamicSharedMemorySize, FL_SMEM);

    // 1) fused front-end: tiled weight conversion + bias prep + LN(ins) + LN(x)
    {
        MegaArgs a;
        a.qkvw = qkvw; a.pw = pw; a.l1w = l1w; a.l2w = l2w;
        a.f1w = f1w; a.p1w = p1w; a.f2w = f2w; a.p2w = p2w;
        a.qb = qb; a.vb = vb; a.f1b = f1b; a.p1b = p1b;
        a.f2b = f2bv; a.p2b = p2b; a.g2 = g2; a.gate = gate;
        a.wqkv = w_qkv; a.wproj = w_proj; a.wl1 = w_l1; a.wl2 = w_l2;
        a.wfc1 = w_fc1; a.wfc2 = w_fc2;
        a.qkvbias = qkvbias; a.fb1c = fb1c; a.cb = cb;
        a.ins = ins; a.ilw = ilw; a.ilb = ilb;
        a.x = x; a.n1w = n1w; a.n1b = n1b;
        a.insln = insln; a.cat = cat;
        mega_pre_kernel<<<MEGA_BLOCKS, 256>>>(a);
    }

    // 2) instruct l1 (gelu)
    {
        EpiParams ep; ep.bias = l1b; ep.outb = hir;
        big_gemm_kernel<0><<<dim3(CQ / 128, (BQ * IQ + 127) / 128), 256, BG_SMEM>>>(
            insln, w_l1, BQ * IQ, CQ, IDQ, ep);
    }
    // 3) instruct l2 -> cat rows [0, I)
    {
        EpiParams ep; ep.bias = l2b; ep.outb = cat;
        big_gemm_kernel<1><<<dim3(CQ / 128, (BQ * IQ + 127) / 128), 256, BG_SMEM>>>(
            hir, w_l2, BQ * IQ, CQ, CQ, ep);
    }

    // 4) qkv projection (v written transposed)
    {
        EpiParams ep; ep.bias = qkvbias; ep.q = qB; ep.k = kB; ep.v = vB;
        big_gemm_kernel<2><<<dim3(3 * CQ / 128, (BQ * SQ + 127) / 128), 256, BG_SMEM>>>(
            cat, w_qkv, BQ * SQ, 3 * CQ, CQ, ep);
    }

    // 5) attention (tcgen05 flash)
    flash_kernel<<<dim3(NQ / 128, HQ, BQ), 128, FL_SMEM>>>(qB, kB, vB, obuf);

    // 6) proj + LayerScale residual -> x1
    {
        EpiParams ep; ep.bias = pb; ep.outf = x1; ep.resid = x; ep.gvec = g1;
        big_gemm_kernel<3><<<dim3(CQ / 128, BQ * NQ / 128), 256, BG_SMEM>>>(
            obuf, w_proj, BQ * NQ, CQ, CQ, ep);
    }

    // 7) y = LN(x1)
    ln_kernel<<<BQ * NQ, 256>>>(x1, n2w, n2b, ybuf, CQ);

    // 8) combined mlp up: h1 = gelu(y @ [fc1;pfc1]^T + [f1b;p1b])
    {
        EpiParams ep; ep.bias = fb1c; ep.outb = h1;
        big_gemm_kernel<0><<<dim3(2 * HIDQ / 128, BQ * NQ / 128), 256, BG_SMEM>>>(
            ybuf, w_fc1, BQ * NQ, 2 * HIDQ, CQ, ep);
    }
    // 9) combined mlp down: out = x1 + h1 @ [g2*fc2 | gate*pfc2]^T + cb
    {
        EpiParams ep; ep.bias = cb; ep.outf = out; ep.resid = x1;
        big_gemm_kernel<4><<<dim3(CQ / 128, BQ * NQ / 128), 256, BG_SMEM>>>(
            h1, w_fc2, BQ * NQ, CQ, 2 * HIDQ, ep);
    }
}

// round 12
// speedup vs baseline: 1.1962x; 1.1962x over previous
#include <cuda_runtime.h>
#include <cuda_bf16.h>
#include <cstdint>
#include <math.h>

typedef __nv_bfloat16 bf16;

#define BQ 4
#define NQ 1024
#define CQ 1024
#define HQ 16
#define IQ 77
#define IDQ 768
#define HDQ 64
#define HIDQ 4096
#define SQ (IQ + NQ)   // 1101
#define SQP 1152       // padded KV length for transposed V

// ---------------- device scratch ----------------
// big-GEMM weights: tiled [NT=N/128][KC=K/64] blocks of 128x64 bf16 (16KB), SW128-swizzled
__device__ __align__(16) bf16 g_wqkv [3*CQ*CQ];
__device__ __align__(16) bf16 g_wproj[CQ*CQ];
__device__ __align__(16) bf16 g_wfc1 [2*HIDQ*CQ];   // [fc1 ; pfc1] stacked on N
__device__ __align__(16) bf16 g_wfc2 [CQ*2*HIDQ];   // [g2*fc2 | gate*pfc2] on K
__device__ __align__(16) bf16 g_wl1  [CQ*IDQ];
__device__ __align__(16) bf16 g_wl2  [CQ*CQ];

__device__ __align__(16) bf16 g_insln[BQ*IQ*IDQ];
__device__ __align__(16) bf16 g_hir  [BQ*IQ*CQ];
__device__ __align__(16) bf16 g_cat  [BQ*SQ*CQ];
__device__ __align__(16) bf16 g_qbuf [BQ*HQ*SQ*HDQ];
__device__ __align__(16) bf16 g_kbuf [BQ*HQ*SQ*HDQ];
__device__ __align__(16) bf16 g_vbuf [BQ*HQ*HDQ*SQP];   // TRANSPOSED [B,H,HD,SQP]
__device__ __align__(16) bf16 g_obuf [BQ*NQ*CQ];
__device__ __align__(16) bf16 g_ybuf [BQ*NQ*CQ];
__device__ __align__(16) bf16 g_h1   [BQ*NQ*2*HIDQ];
__device__ __align__(16) float g_x1  [BQ*NQ*CQ];
__device__ float g_qkvbias[3*CQ];
__device__ float g_fb1c[2*HIDQ];
__device__ float g_cb[CQ];

// ---------------- helpers ----------------
__device__ __forceinline__ uint32_t smem_u32(const void* p) {
    return (uint32_t)__cvta_generic_to_shared(p);
}
__device__ __forceinline__ void cpa16(uint32_t s, const void* g, bool p) {
    int sz = p ? 16 : 0;
    asm volatile("cp.async.cg.shared.global [%0], [%1], 16, %2;"
                 :: "r"(s), "l"(g), "r"(sz));
}
__device__ __forceinline__ void cp_commit() { asm volatile("cp.async.commit_group;"); }
template <int N_> __device__ __forceinline__ void cp_wait() {
    asm volatile("cp.async.wait_group %0;" :: "n"(N_));
}
__device__ __forceinline__ void ldm4(uint32_t* r, uint32_t a) {
    asm volatile("ldmatrix.sync.aligned.m8n8.x4.shared.b16 {%0,%1,%2,%3}, [%4];"
        : "=r"(r[0]), "=r"(r[1]), "=r"(r[2]), "=r"(r[3]) : "r"(a));
}
__device__ __forceinline__ void mma_bf16(float* d, const uint32_t* a, const uint32_t* b) {
    asm volatile("mma.sync.aligned.m16n8k16.row.col.f32.bf16.bf16.f32 "
        "{%0,%1,%2,%3}, {%4,%5,%6,%7}, {%8,%9}, {%0,%1,%2,%3};"
        : "+f"(d[0]), "+f"(d[1]), "+f"(d[2]), "+f"(d[3])
        : "r"(a[0]), "r"(a[1]), "r"(a[2]), "r"(a[3]), "r"(b[0]), "r"(b[1]));
}
__device__ __forceinline__ float gelu_exact(float x) {
    return 0.5f * x * (1.0f + erff(x * 0.70710678118654752f));
}
__device__ __forceinline__ uint32_t packbf(float a, float b) {
    __nv_bfloat162 t = __floats2bfloat162_rn(a, b);
    return *reinterpret_cast<uint32_t*>(&t);
}

// tiled weight addressing: element (n, k) of an [N][K] weight; 128x64 blocks, KC = K/64
__device__ __forceinline__ size_t wt_byteoff(int KC, int n, int k) {
    int nt = n >> 7, rl = n & 127, kc = k >> 6, cl = k & 63;
    size_t blk = ((size_t)(nt * KC + kc)) * 16384;
    uint32_t off = (uint32_t)(rl * 128 + cl * 2);
    uint32_t sw = off ^ ((off >> 3) & 0x70);
    return blk + sw;
}

#if defined(__CUDA_ARCH_FEAT_SM103_ALL)
#define HAS_TG 1
__device__ __forceinline__ uint32_t elect1() {
    uint32_t p;
    asm volatile("{\n\t.reg .pred p;\n\telect.sync _|p, 0xFFFFFFFF;\n\tselp.b32 %0, 1, 0, p;\n\t}"
        : "=r"(p));
    return p;
}
__device__ __forceinline__ void mbar_init(uint32_t a, uint32_t cnt) {
    asm volatile("mbarrier.init.shared.b64 [%0], %1;" :: "r"(a), "r"(cnt) : "memory");
}
__device__ __forceinline__ void mbar_wait(uint32_t a, int parity) {
    asm volatile("{\n\t.reg .pred P;\n\tWL%=:\n\t"
        "mbarrier.try_wait.parity.shared::cta.b64 P, [%0], %1;\n\t"
        "@!P bra WL%=;\n\t}" :: "r"(a), "r"(parity) : "memory");
}
__device__ __forceinline__ void mbar_arrive(uint32_t a) {
    asm volatile("mbarrier.arrive.shared.b64 _, [%0];" :: "r"(a) : "memory");
}
__device__ __forceinline__ void mbar_expect_tx(uint32_t a, uint32_t bytes) {
    asm volatile("mbarrier.arrive.expect_tx.shared.b64 _, [%0], %1;"
        :: "r"(a), "r"(bytes) : "memory");
}
__device__ __forceinline__ void bulk_ld(uint32_t dst, const void* src, uint32_t bytes, uint32_t mbar) {
    asm volatile("cp.async.bulk.shared::cluster.global.mbarrier::complete_tx::bytes "
        "[%0], [%1], %2, [%3];"
        :: "r"(dst), "l"(src), "r"(bytes), "r"(mbar) : "memory");
}
__device__ __forceinline__ void tg_mma_f16_ss(uint32_t d, uint64_t ad, uint64_t bd,
                                              uint32_t idesc, bool en) {
    uint32_t e = en ? 1u : 0u;
    asm volatile("{\n\t.reg .pred p;\n\tsetp.ne.u32 p, %4, 0;\n\t"
        "tcgen05.mma.cta_group::1.kind::f16 [%0], %1, %2, %3, {%5,%5,%5,%5}, p;\n\t}"
        :: "r"(d), "l"(ad), "l"(bd), "r"(idesc), "r"(e), "r"(0u) : "memory");
}
__device__ __forceinline__ void tg_commit(uint32_t mbar) {
    asm volatile("tcgen05.commit.cta_group::1.mbarrier::arrive::one.shared::cluster.b64 [%0];"
        :: "r"(mbar) : "memory");
}
__device__ __forceinline__ void tg_ld32(uint32_t* r, uint32_t a) {
    asm volatile("tcgen05.ld.sync.aligned.32x32b.x32.b32 "
        "{%0,%1,%2,%3,%4,%5,%6,%7,%8,%9,%10,%11,%12,%13,%14,%15,"
        "%16,%17,%18,%19,%20,%21,%22,%23,%24,%25,%26,%27,%28,%29,%30,%31}, [%32];"
        : "=r"(r[0]),"=r"(r[1]),"=r"(r[2]),"=r"(r[3]),"=r"(r[4]),"=r"(r[5]),"=r"(r[6]),"=r"(r[7]),
          "=r"(r[8]),"=r"(r[9]),"=r"(r[10]),"=r"(r[11]),"=r"(r[12]),"=r"(r[13]),"=r"(r[14]),"=r"(r[15]),
          "=r"(r[16]),"=r"(r[17]),"=r"(r[18]),"=r"(r[19]),"=r"(r[20]),"=r"(r[21]),"=r"(r[22]),"=r"(r[23]),
          "=r"(r[24]),"=r"(r[25]),"=r"(r[26]),"=r"(r[27]),"=r"(r[28]),"=r"(r[29]),"=r"(r[30]),"=r"(r[31])
        : "r"(a));
}
#define TG_WAIT_LD()  asm volatile("tcgen05.wait::ld.sync.aligned;" ::: "memory")
#define TG_FENCE_AFTER() asm volatile("tcgen05.fence::after_thread_sync;" ::: "memory")
#define TG_ALLOC(sm, n) asm volatile("tcgen05.alloc.cta_group::1.sync.aligned.shared::cta.b32 [%0], %1;" :: "r"(sm), "r"((uint32_t)(n)) : "memory")
#define TG_DEALLOC(t, n) asm volatile("tcgen05.dealloc.cta_group::1.sync.aligned.b32 %0, %1;" :: "r"(t), "r"((uint32_t)(n)))
#define TG_RELINQ() asm volatile("tcgen05.relinquish_alloc_permit.cta_group::1.sync.aligned;")

static __device__ __forceinline__ uint64_t mk_desc(uint32_t addr) {
    return ((uint64_t)2 << 61) | ((uint64_t)1 << 46) | ((uint64_t)64 << 32) |
           ((uint64_t)1 << 16) | (uint64_t)((addr >> 4) & 0x3FFF);
}
#endif

// ---------------- fused front-end: tiled weight cvt + bias prep + LN(ins) + LN(x) ----
struct MegaArgs {
    const float *qkvw, *pw, *l1w, *l2w, *f1w, *p1w, *f2w, *p2w;
    const float *qb, *vb, *f1b, *p1b, *f2b, *p2b, *g2, *gate;
    bf16 *wqkv, *wproj, *wl1, *wl2, *wfc1, *wfc2;
    float *qkvbias, *fb1c, *cb;
    const float *ins, *ilw, *ilb, *x, *n1w, *n1b;
    bf16 *insln, *cat;
};

#define CVT_V4_BLOCKS 22272
#define CVT_MISC_BLOCKS 48
#define LNI_BLOCKS (BQ * IQ)     // 308
#define LNX_BLOCKS (BQ * NQ)     // 4096
#define MEGA_BLOCKS (CVT_V4_BLOCKS + CVT_MISC_BLOCKS + LNI_BLOCKS + LNX_BLOCKS)

__device__ __forceinline__ void cvt_tiled4(const float* row, bf16* dst, int KC,
                                           int n, int k, float s) {
    float4 v = *(const float4*)(row + k);
    uint2 o;
    o.x = packbf(v.x * s, v.y * s);
    o.y = packbf(v.z * s, v.w * s);
    *(uint2*)((char*)dst + wt_byteoff(KC, n, k)) = o;
}

__device__ void ln_row(const float* __restrict__ p, const float* __restrict__ w,
                       const float* __restrict__ bia, bf16* __restrict__ op,
                       int D, float* sm) {
    int tid = threadIdx.x;
    float s = 0.0f, s2 = 0.0f;
    for (int i = tid; i < D; i += 256) { float v = p[i]; s += v; s2 += v * v; }
    #pragma unroll
    for (int o = 16; o; o >>= 1) {
        s  += __shfl_xor_sync(0xffffffffu, s, o);
        s2 += __shfl_xor_sync(0xffffffffu, s2, o);
    }
    int warp = tid >> 5, lane = tid & 31;
    if (lane == 0) { sm[warp] = s; sm[warp + 8] = s2; }
    __syncthreads();
    s = 0.0f; s2 = 0.0f;
    #pragma unroll
    for (int i = 0; i < 8; i++) { s += sm[i]; s2 += sm[i + 8]; }
    float m = s / D;
    float var = s2 / D - m * m;
    float inv = rsqrtf(var + 1e-5f);
    for (int i = tid; i < D; i += 256)
        op[i] = __float2bfloat16((p[i] - m) * inv * w[i] + bia[i]);
}

__global__ void mega_pre_kernel(MegaArgs a) {
    __shared__ float sm[16];
    int bid = blockIdx.x;
    int tid = threadIdx.x;
    if (bid < CVT_V4_BLOCKS) {
        int i = bid * 256 + tid;
        if (i < 786432) {                       // wqkv 3072x1024, KC=16
            int n = i >> 8, k = (i & 255) * 4;
            cvt_tiled4(a.qkvw + (size_t)n * CQ, a.wqkv, 16, n, k, 1.0f);
        } else if (i < 1048576) {               // wproj 1024x1024, KC=16
            int j = i - 786432;
            int n = j >> 8, k = (j & 255) * 4;
            cvt_tiled4(a.pw + (size_t)n * CQ, a.wproj, 16, n, k, 1.0f);
        } else if (i < 1245184) {               // wl1 1024x768, KC=12
            int j = i - 1048576;
            int n = j / 192, k = (j % 192) * 4;
            cvt_tiled4(a.l1w + (size_t)n * IDQ, a.wl1, 12, n, k, 1.0f);
        } else if (i < 1507328) {               // wl2 1024x1024, KC=16
            int j = i - 1245184;
            int n = j >> 8, k = (j & 255) * 4;
            cvt_tiled4(a.l2w + (size_t)n * CQ, a.wl2, 16, n, k, 1.0f);
        } else if (i < 2555904) {               // fc1 rows [0,4096), KC=16
            int j = i - 1507328;
            int n = j >> 8, k = (j & 255) * 4;
            cvt_tiled4(a.f1w + (size_t)n * CQ, a.wfc1, 16, n, k, 1.0f);
        } else if (i < 3604480) {               // pfc1 rows [4096,8192), KC=16
            int j = i - 2555904;
            int n = j >> 8, k = (j & 255) * 4;
            cvt_tiled4(a.p1w + (size_t)n * CQ, a.wfc1, 16, n + HIDQ, k, 1.0f);
        } else if (i < 4653056) {               // g2*fc2 cols [0,4096), KC=128
            int j = i - 3604480;
            int n = j >> 10, k = (j & 1023) * 4;
            float s = a.g2[n];
            float4 v = *(const float4*)(a.f2w + (size_t)n * HIDQ + k);
            uint2 o;
            o.x = packbf(v.x * s, v.y * s);
            o.y = packbf(v.z * s, v.w * s);
            *(uint2*)((char*)a.wfc2 + wt_byteoff(128, n, k)) = o;
        } else {                                // gate*pfc2 cols [4096,8192), KC=128
            int j = i - 4653056;
            int n = j >> 10, kk = (j & 1023) * 4;
            float s = a.gate[0];
            float4 v = *(const float4*)(a.p2w + (size_t)n * HIDQ + kk);
            uint2 o;
            o.x = packbf(v.x * s, v.y * s);
            o.y = packbf(v.z * s, v.w * s);
            *(uint2*)((char*)a.wfc2 + wt_byteoff(128, n, kk + HIDQ)) = o;
        }
    } else if (bid < CVT_V4_BLOCKS + CVT_MISC_BLOCKS) {
        int t = (bid - CVT_V4_BLOCKS) * 256 + tid;
        if (t < 3072) {
            float v = 0.0f;
            if (t < CQ) v = a.qb[t];
            else if (t >= 2 * CQ) v = a.vb[t - 2 * CQ];
            a.qkvbias[t] = v;
        } else if (t < 11264) {
            int j = t - 3072;
            a.fb1c[j] = (j < HIDQ) ? a.f1b[j] : a.p1b[j - HIDQ];
        } else {
            int j = t - 11264;
            a.cb[j] = a.g2[j] * a.f2b[j] + a.gate[0] * a.p2b[j];
        }
    } else if (bid < CVT_V4_BLOCKS + CVT_MISC_BLOCKS + LNI_BLOCKS) {
        int row = bid - (CVT_V4_BLOCKS + CVT_MISC_BLOCKS);
        ln_row(a.ins + (size_t)row * IDQ, a.ilw, a.ilb,
               a.insln + (size_t)row * IDQ, IDQ, sm);
    } else {
        int row = bid - (CVT_V4_BLOCKS + CVT_MISC_BLOCKS + LNI_BLOCKS);
        int bb = row >> 10, n = row & 1023;
        ln_row(a.x + (size_t)row * CQ, a.n1w, a.n1b,
               a.cat + (size_t)(bb * SQ + IQ + n) * CQ, CQ, sm);
    }
}

// ---------------- LayerNorm (standalone — LN2 only) ----------------
__global__ void ln_kernel(const float* __restrict__ in, const float* __restrict__ w,
                          const float* __restrict__ bia, bf16* __restrict__ out, int D) {
    __shared__ float sm[16];
    int row = blockIdx.x;
    ln_row(in + (size_t)row * D, w, bia, out + (size_t)row * D, D, sm);
}

// ---------------- epilogue params ----------------
struct EpiParams {
    const float* bias  = nullptr;
    bf16*  outb        = nullptr;
    float* outf        = nullptr;
    const float* resid = nullptr;
    const float* gvec  = nullptr;
    bf16* q = nullptr; bf16* k = nullptr; bf16* v = nullptr;
};

// ---------------- big GEMM: warp-specialized tcgen05 pipeline ----------------
// 128x128 tile, BK=64, 3 stages. Warps 0-3: A cp.async producers + tid0 B bulk;
// warp 4: MMA issue. No __syncthreads in the mainloop.
// full[s] count=129 (128 A-arrivals + expect_tx arrival); done[s] count=1 (commit).
// MODE 0: outb = gelu(acc+bias) ; 1: cat scatter ; 2: qkv split (V transposed) ;
// MODE 3: outf = resid + gvec*acc+bias ; 4: outf = resid + acc + bias
#define BG_SMEM 100352

template <int MODE>
__global__ __launch_bounds__(256, 2)
void big_gemm_kernel(const bf16* __restrict__ A, const bf16* __restrict__ W,
                     int M, int N, int K, EpiParams ep) {
#if defined(__CUDA_ARCH_FEAT_SM103_ALL)
    extern __shared__ char dsm[];
    char* base = (char*)(((uintptr_t)dsm + 1023) & ~(uintptr_t)1023);
    const uint32_t sb = smem_u32(base);
    const int tid = threadIdx.x, warp = tid >> 5;
    const int mbase = blockIdx.y * 128, nbase = blockIdx.x * 128;
    const int KC = K >> 6;
    const int NK = KC;

    if (warp == 0) { TG_ALLOC(sb, 128); }
    if (tid == 0) {
        mbar_init(sb + 8, 129);   // full 0..2
        mbar_init(sb + 16, 129);
        mbar_init(sb + 24, 129);
        mbar_init(sb + 32, 1);    // done 0..2
        mbar_init(sb + 40, 1);
        mbar_init(sb + 48, 1);
    }
    __syncthreads();
    uint32_t tmem;
    asm volatile("ld.shared.b32 %0, [%1];" : "=r"(tmem) : "r"(sb));
    if (warp == 0) TG_RELINQ();

    auto stA = [&](int s) -> uint32_t { return sb + 2048 + s * 32768; };
    auto fullb = [&](int s) -> uint32_t { return sb + 8 + 8 * s; };
    auto doneb = [&](int s) -> uint32_t { return sb + 32 + 8 * s; };

    if (tid < 128) {
        // -------- producers (warps 0-3) --------
        for (int kt = 0; kt < NK; kt++) {
            int s = kt % 3;
            if (kt >= 3) mbar_wait(doneb(s), ((kt - 3) / 3) & 1);
            uint32_t a0 = stA(s);
            int k0 = kt << 6;
            #pragma unroll
            for (int i = 0; i < 8; i++) {
                int idx = tid + i * 128;
                int r = idx >> 3, cch = idx & 7;
                uint32_t off = (uint32_t)(r * 128 + cch * 16);
                uint32_t sw = off ^ ((off >> 3) & 0x70);
                bool pa = (mbase + r) < M;
                const bf16* ga = pa ? (A + (size_t)(mbase + r) * K + k0 + cch * 8) : A;
                cpa16(a0 + sw, ga, pa);
            }
            cp_commit();
            if (tid == 0) {
                mbar_expect_tx(fullb(s), 16384);
                bulk_ld(a0 + 16384,
                        (const char*)W + ((size_t)(blockIdx.x * KC + kt)) * 16384,
                        16384, fullb(s));
            }
            if (kt >= 1) {
                cp_wait<1>();
                asm volatile("fence.proxy.async.shared::cta;" ::: "memory");
                mbar_arrive(fullb((kt - 1) % 3));
            }
        }
        cp_wait<0>();
        asm volatile("fence.proxy.async.shared::cta;" ::: "memory");
        mbar_arrive(fullb((NK - 1) % 3));
    } else if (warp == 4) {
        // -------- MMA consumer --------
        const uint32_t lead = elect1();
        const uint32_t idesc = (1u << 4) | (1u << 7) | (1u << 10) | (16u << 17) | (8u << 24);
        for (int kt = 0; kt < NK; kt++) {
            int s = kt % 3;
            mbar_wait(fullb(s), (kt / 3) & 1);
            if (lead) {
                uint64_t ad = mk_desc(stA(s));
                uint64_t bd = mk_desc(stA(s) + 16384);
                #pragma unroll
                for (int stp = 0; stp < 4; stp++)
                    tg_mma_f16_ss(tmem, ad + stp * 2, bd + stp * 2, idesc,
                                  (kt > 0) || (stp > 0));
                tg_commit(doneb(s));
            }
        }
    }

    // all threads: wait for the final chunk's MMA completion
    {
        int sl = (NK - 1) % 3;
        int cnt = (NK - 1 - sl) / 3 + 1;
        mbar_wait(doneb(sl), (cnt - 1) & 1);
    }
    TG_FENCE_AFTER();
    __syncthreads();

    if (tid < 128) {
        const int grow = mbase + tid;
        #pragma unroll
        for (int cc = 0; cc < 4; cc++) {
            uint32_t regs[32];
            tg_ld32(regs, tmem + cc * 32);
            TG_WAIT_LD();
            if (grow < M) {
                const int c0 = nbase + cc * 32;
                float vals[32];
                #pragma unroll
                for (int c = 0; c < 32; c++)
                    vals[c] = __uint_as_float(regs[c]) + ep.bias[c0 + c];

                if (MODE == 0) {
                    uint32_t pk[16];
                    #pragma unroll
                    for (int c = 0; c < 16; c++)
                        pk[c] = packbf(gelu_exact(vals[2*c]), gelu_exact(vals[2*c+1]));
                    uint4* dst = (uint4*)(ep.outb + (size_t)grow * N + c0);
                    #pragma unroll
                    for (int q = 0; q < 4; q++)
                        dst[q] = make_uint4(pk[4*q], pk[4*q+1], pk[4*q+2], pk[4*q+3]);
                } else if (MODE == 1) {
                    int bb = grow / IQ, ii = grow % IQ;
                    uint32_t pk[16];
                    #pragma unroll
                    for (int c = 0; c < 16; c++)
                        pk[c] = packbf(vals[2*c], vals[2*c+1]);
                    uint4* dst = (uint4*)(ep.outb + (size_t)(bb * SQ + ii) * CQ + c0);
                    #pragma unroll
                    for (int q = 0; q < 4; q++)
                        dst[q] = make_uint4(pk[4*q], pk[4*q+1], pk[4*q+2], pk[4*q+3]);
                } else if (MODE == 2) {
                    int bb = grow / SQ, s = grow % SQ;
                    int sec = c0 >> 10, hh = (c0 & 1023) >> 6, d0 = c0 & 63;
                    if (sec == 2) {
                        bf16* vt = ep.v + (size_t)(bb * HQ + hh) * HDQ * SQP;
                        #pragma unroll
                        for (int c = 0; c < 32; c++)
                            vt[(size_t)(d0 + c) * SQP + s] = __float2bfloat16(vals[c]);
                    } else {
                        size_t off = ((size_t)(bb * HQ + hh) * SQ + s) * HDQ + d0;
                        bf16* dstp; float scl = 1.0f;
                        if (sec == 0) { dstp = ep.q + off; scl = 0.125f; }
                        else          { dstp = ep.k + off; }
                        uint32_t pk[16];
                        #pragma unroll
                        for (int c = 0; c < 16; c++)
                            pk[c] = packbf(vals[2*c] * scl, vals[2*c+1] * scl);
                        uint4* dst = (uint4*)dstp;
                        #pragma unroll
                        for (int q = 0; q < 4; q++)
                            dst[q] = make_uint4(pk[4*q], pk[4*q+1], pk[4*q+2], pk[4*q+3]);
                    }
                } else if (MODE == 3) {
                    const float4* rs = (const float4*)(ep.resid + (size_t)grow * CQ + c0);
                    float4* dst = (float4*)(ep.outf + (size_t)grow * CQ + c0);
                    #pragma unroll
                    for (int q = 0; q < 8; q++) {
                        float4 rv = rs[q];
                        float4 o;
                        o.x = rv.x + ep.gvec[c0 + 4*q + 0] * vals[4*q + 0];
                        o.y = rv.y + ep.gvec[c0 + 4*q + 1] * vals[4*q + 1];
                        o.z = rv.z + ep.gvec[c0 + 4*q + 2] * vals[4*q + 2];
                        o.w = rv.w + ep.gvec[c0 + 4*q + 3] * vals[4*q + 3];
                        dst[q] = o;
                    }
                } else {
                    const float4* rs = (const float4*)(ep.resid + (size_t)grow * CQ + c0);
                    float4* dst = (float4*)(ep.outf + (size_t)grow * CQ + c0);
                    #pragma unroll
                    for (int q = 0; q < 8; q++) {
                        float4 rv = rs[q];
                        float4 o;
                        o.x = rv.x + vals[4*q + 0];
                        o.y = rv.y + vals[4*q + 1];
                        o.z = rv.z + vals[4*q + 2];
                        o.w = rv.w + vals[4*q + 3];
                        dst[q] = o;
                    }
                }
            }
        }
    }
    __syncthreads();
    if (warp == 0) TG_DEALLOC(tmem, 128);
#else
    // ======== mma.sync fallback (tiled B addressing) ========
    extern __shared__ bf16 smem[];
    bf16* sA = smem;
    bf16* sB = smem + 3 * 5120;
    const int tid  = threadIdx.x;
    const int lane = tid & 31, warp = tid >> 5;
    const int wm = warp & 1, wn = warp >> 1;
    const int mbase = blockIdx.y * 128, nbase = blockIdx.x * 128;
    const int KC = K >> 6;
    const int lr = tid >> 2, lc = (tid & 3) * 8;

    float acc[4][4][4];
    #pragma unroll
    for (int a = 0; a < 4; a++)
        #pragma unroll
        for (int b = 0; b < 4; b++)
            #pragma unroll
            for (int c = 0; c < 4; c++) acc[a][b][c] = 0.0f;

    const int NK = K >> 5;

    auto baddr = [&](int n, int k) -> const bf16* {
        return (const bf16*)((const char*)W + wt_byteoff(KC, n, k));
    };
    auto issue = [&](int kt) {
        int k0 = kt << 5;
        int st = kt % 3;
        bf16* dA = sA + st * 5120;
        bf16* dB = sB + st * 5120;
        bool p1 = (mbase + lr) < M;
        bool p2 = (mbase + lr + 64) < M;
        const bf16* ga1 = p1 ? (A + (size_t)(mbase + lr) * K + k0 + lc) : A;
        const bf16* ga2 = p2 ? (A + (size_t)(mbase + lr + 64) * K + k0 + lc) : A;
        cpa16(smem_u32(dA + lr * 40 + lc), ga1, p1);
        cpa16(smem_u32(dA + (lr + 64) * 40 + lc), ga2, p2);
        cpa16(smem_u32(dB + lr * 40 + lc), baddr(nbase + lr, k0 + lc), true);
        cpa16(smem_u32(dB + (lr + 64) * 40 + lc), baddr(nbase + lr + 64, k0 + lc), true);
    };

    issue(0); cp_commit();
    issue(1); cp_commit();

    for (int kt = 0; kt < NK; kt++) {
        if (kt + 1 < NK) cp_wait<1>(); else cp_wait<0>();
        __syncthreads();
        if (kt + 2 < NK) issue(kt + 2);
        cp_commit();

        const int st = kt % 3;
        const uint32_t a0 = smem_u32(sA + st * 5120);
        const uint32_t b0 = smem_u32(sB + st * 5120);
        #pragma unroll
        for (int ks = 0; ks < 2; ks++) {
            int kc = ks * 16;
            uint32_t af[4][4];
            #pragma unroll
            for (int im = 0; im < 4; im++) {
                int row = wm * 64 + im * 16 + (lane & 15);
                int col = kc + ((lane >> 4) << 3);
                ldm4(af[im], a0 + (uint32_t)((row * 40 + col) * 2));
            }
            uint32_t bfr[4][2];
            #pragma unroll
            for (int ib = 0; ib < 2; ib++) {
                int g = lane >> 3;
                int row = wn * 32 + ib * 16 + ((g >> 1) << 3) + (lane & 7);
                int col = kc + ((g & 1) << 3);
                uint32_t r4[4];
                ldm4(r4, b0 + (uint32_t)((row * 40 + col) * 2));
                bfr[2*ib][0] = r4[0]; bfr[2*ib][1] = r4[1];
                bfr[2*ib+1][0] = r4[2]; bfr[2*ib+1][1] = r4[3];
            }
            #pragma unroll
            for (int im = 0; im < 4; im++)
                #pragma unroll
                for (int in_ = 0; in_ < 4; in_++)
                    mma_bf16(acc[im][in_], af[im], bfr[in_]);
        }
    }

    #pragma unroll
    for (int im = 0; im < 4; im++)
        #pragma unroll
        for (int in_ = 0; in_ < 4; in_++)
            #pragma unroll
            for (int j = 0; j < 4; j++) {
                int r = mbase + wm * 64 + im * 16 + (lane >> 2) + ((j >> 1) << 3);
                int c = nbase + wn * 32 + in_ * 8 + ((lane & 3) << 1) + (j & 1);
                if (r >= M) continue;
                float v = acc[im][in_][j] + ep.bias[c];
                if (MODE == 0) {
                    ep.outb[(size_t)r * N + c] = __float2bfloat16(gelu_exact(v));
                } else if (MODE == 1) {
                    int bb = r / IQ, ii = r % IQ;
                    ep.outb[(size_t)(bb * SQ + ii) * CQ + c] = __float2bfloat16(v);
                } else if (MODE == 2) {
                    int bb = r / SQ, s = r % SQ;
                    int sec = c >> 10, hh = (c & 1023) >> 6, d = c & 63;
                    if (sec == 2) {
                        ep.v[((size_t)(bb * HQ + hh) * HDQ + d) * SQP + s] = __float2bfloat16(v);
                    } else {
                        size_t dst = ((size_t)(bb * HQ + hh) * SQ + s) * HDQ + d;
                        if (sec == 0) ep.q[dst] = __float2bfloat16(v * 0.125f);
                        else          ep.k[dst] = __float2bfloat16(v);
                    }
                } else if (MODE == 3) {
                    ep.outf[(size_t)r * CQ + c] = ep.resid[(size_t)r * CQ + c] + ep.gvec[c] * v;
                } else if (MODE == 4) {
                    ep.outf[(size_t)r * CQ + c] = ep.resid[(size_t)r * CQ + c] + v;
                }
            }
#endif
}

// ---------------- flash attention (round-8 tcgen05 version) ----------------
#define NCH ((SQ + 63) / 64)   // 18
#define FL_SMEM 84992

__global__ __launch_bounds__(128, 2)
void flash_kernel(const bf16* __restrict__ Q, const bf16* __restrict__ K,
                  const bf16* __restrict__ Vt, bf16* __restrict__ O) {
#if defined(__CUDA_ARCH_FEAT_SM103_ALL)
    extern __shared__ char dsm[];
    char* base = (char*)(((uintptr_t)dsm + 1023) & ~(uintptr_t)1023);
    const uint32_t sb = smem_u32(base);
    const int tid = threadIdx.x, warp = tid >> 5;
    const int q0 = blockIdx.x * 128;
    const int h = blockIdx.y, b = blockIdx.z;
    const char* qbase = (const char*)(Q + ((size_t)(b * HQ + h) * SQ + IQ + q0) * HDQ);
    const char* kbase = (const char*)(K + (size_t)(b * HQ + h) * SQ * HDQ);
    const char* vtbase = (const char*)(Vt + (size_t)(b * HQ + h) * HDQ * SQP);

    if (warp == 0) TG_ALLOC(sb, 128);
    if (tid == 0) { mbar_init(sb + 8, 1); mbar_init(sb + 16, 1); }
    __syncthreads();
    uint32_t tmem;
    asm volatile("ld.shared.b32 %0, [%1];" : "=r"(tmem) : "r"(sb));
    if (warp == 0) TG_RELINQ();

    const uint32_t sQ = sb + 1024;
    const uint32_t sP = sQ + 16384;
    const uint32_t sK = sP + 16384;
    const uint32_t sV = sK + 24576;

    #pragma unroll
    for (int i = 0; i < 8; i++) {
        int idx = tid + i * 128;
        int r = idx >> 3, cb = (idx & 7) * 16;
        uint32_t off = (uint32_t)(r * 128 + cb);
        uint32_t sw = off ^ ((off >> 3) & 0x70);
        *(uint4*)(base + 1024 + sw) = *(const uint4*)(qbase + (size_t)r * 128 + cb);
    }
    asm volatile("fence.proxy.async.shared::cta;" ::: "memory");

    auto issueKV = [&](int ci) {
        int st = ci % 3;
        int s0 = ci * 64;
        #pragma unroll
        for (int i = 0; i < 4; i++) {
            int idx = tid + i * 128;
            int r = idx >> 3, cb = (idx & 7) * 16;
            uint32_t off = (uint32_t)(r * 128 + cb);
            uint32_t sw = off ^ ((off >> 3) & 0x70);
            bool pk = (s0 + r) < SQ;
            const char* gk = pk ? (kbase + (size_t)(s0 + r) * 128 + cb) : kbase;
            cpa16(sK + st * 8192 + sw, gk, pk);
            const char* gv = vtbase + (size_t)r * (SQP * 2) + (size_t)s0 * 2 + cb;
            cpa16(sV + st * 8192 + sw, gv, true);
        }
        cp_commit();
    };

    const uint32_t lead = (warp == 0) ? elect1() : 0;
    const uint32_t idesc = (1u << 4) | (1u << 7) | (1u << 10) | (8u << 17) | (8u << 24);

    issueKV(0);
    issueKV(1);

    float rsum = 0.0f;
    const uint64_t qd = mk_desc(sQ);
    const uint64_t pd = mk_desc(sP);

    for (int ci = 0; ci < NCH; ci++) {
        int st = ci % 3;
        int s0 = ci * 64;
        if (ci + 1 < NCH) cp_wait<1>(); else cp_wait<0>();
        __syncthreads();

        if (warp == 0 && lead) {
            uint64_t kd = mk_desc(sK + st * 8192);
            #pragma unroll
            for (int stp = 0; stp < 4; stp++)
                tg_mma_f16_ss(tmem, qd + stp * 2, kd + stp * 2, idesc, stp > 0);
            tg_commit(sb + 8);
        }
        mbar_wait(sb + 8, ci & 1);
        TG_FENCE_AFTER();

        if (ci + 2 < NCH) issueKV(ci + 2);

        uint32_t sr[32], sr2[32];
        tg_ld32(sr, tmem);
        tg_ld32(sr2, tmem + 32);
        TG_WAIT_LD();
        uint32_t pk[32];
        #pragma unroll
        for (int j = 0; j < 16; j++) {
            float e0 = (s0 + 2*j     < SQ) ? __expf(__uint_as_float(sr[2*j]))     : 0.0f;
            float e1 = (s0 + 2*j + 1 < SQ) ? __expf(__uint_as_float(sr[2*j + 1])) : 0.0f;
            rsum += e0 + e1;
            pk[j] = packbf(e0, e1);
        }
        #pragma unroll
        for (int j = 0; j < 16; j++) {
            float e0 = (s0 + 32 + 2*j     < SQ) ? __expf(__uint_as_float(sr2[2*j]))     : 0.0f;
            float e1 = (s0 + 32 + 2*j + 1 < SQ) ? __expf(__uint_as_float(sr2[2*j + 1])) : 0.0f;
            rsum += e0 + e1;
            pk[16 + j] = packbf(e0, e1);
        }
        #pragma unroll
        for (int cbk = 0; cbk < 8; cbk++) {
            uint32_t off = (uint32_t)(tid * 128 + cbk * 16);
            uint32_t sw = off ^ ((off >> 3) & 0x70);
            *(uint4*)(base + (sP - sb) + sw) =
                make_uint4(pk[4*cbk], pk[4*cbk+1], pk[4*cbk+2], pk[4*cbk+3]);
        }
        asm volatile("fence.proxy.async.shared::cta;" ::: "memory");
        __syncthreads();

        if (warp == 0 && lead) {
            uint64_t vd = mk_desc(sV + st * 8192);
            #pragma unroll
            for (int stp = 0; stp < 4; stp++)
                tg_mma_f16_ss(tmem + 64, pd + stp * 2, vd + stp * 2, idesc,
                              (ci > 0) || (stp > 0));
            if (ci == NCH - 1) tg_commit(sb + 16);
        }
    }

    mbar_wait(sb + 16, 0);
    TG_FENCE_AFTER();

    uint32_t orr[32], orr2[32];
    tg_ld32(orr, tmem + 64);
    tg_ld32(orr2, tmem + 96);
    TG_WAIT_LD();
    float inv = 1.0f / rsum;
    uint32_t po[32];
    #pragma unroll
    for (int j = 0; j < 16; j++)
        po[j] = packbf(__uint_as_float(orr[2*j]) * inv, __uint_as_float(orr[2*j+1]) * inv);
    #pragma unroll
    for (int j = 0; j < 16; j++)
        po[16+j] = packbf(__uint_as_float(orr2[2*j]) * inv, __uint_as_float(orr2[2*j+1]) * inv);
    uint4* orow = (uint4*)(O + (size_t)(b * NQ + q0 + tid) * CQ + h * HDQ);
    #pragma unroll
    for (int q = 0; q < 8; q++)
        orow[q] = make_uint4(po[4*q], po[4*q+1], po[4*q+2], po[4*q+3]);

    __syncthreads();
    if (warp == 0) TG_DEALLOC(tmem, 128);
#else
    // ---- mma.sync fallback: two sequential 64-row subtiles, V from Vt ----
    extern __shared__ bf16 fsm[];
    bf16* sQs = fsm;
    bf16* sKb = fsm + 4608;
    bf16* sVb = sKb + 3 * 4608;
    const int tid = threadIdx.x, lane = tid & 31, warp = tid >> 5;
    const int h = blockIdx.y, b = blockIdx.z;
    const bf16* kbase = K + (size_t)(b * HQ + h) * SQ * HDQ;
    const bf16* vtbase = Vt + (size_t)(b * HQ + h) * HDQ * SQP;

    for (int sub = 0; sub < 2; sub++) {
        const int q0 = blockIdx.x * 128 + sub * 64;
        const bf16* qbase = Q + ((size_t)(b * HQ + h) * SQ + IQ + q0) * HDQ;

        #pragma unroll
        for (int i = 0; i < 4; i++) {
            int chunk = tid + i * 128;
            int r = chunk >> 3, c = (chunk & 7) * 8;
            *(uint4*)(sQs + r * 72 + c) = *(const uint4*)(qbase + (size_t)r * HDQ + c);
        }

        auto issueKV = [&](int ci) {
            int s0 = ci * 64;
            int bs = ci % 3;
            #pragma unroll
            for (int i = 0; i < 4; i++) {
                int chunk = tid + i * 128;
                int r = chunk >> 3, c = (chunk & 7) * 8;
                bool p = (s0 + r) < SQ;
                const bf16* gk = p ? (kbase + (size_t)(s0 + r) * HDQ + c) : kbase;
                cpa16(smem_u32(sKb + bs * 4608 + r * 72 + c), gk, p);
                const bf16* gv = vtbase + (size_t)r * SQP + s0 + c;
                cpa16(smem_u32(sVb + bs * 4608 + r * 72 + c), gv, true);
            }
        };

        float oacc[8][4];
        #pragma unroll
        for (int t = 0; t < 8; t++)
            #pragma unroll
            for (int j = 0; j < 4; j++) oacc[t][j] = 0.0f;
        float rmax[2] = {-1e30f, -1e30f}, rsum[2] = {0.0f, 0.0f};

        const uint32_t sQ0 = smem_u32(sQs);

        issueKV(0); cp_commit();
        issueKV(1); cp_commit();

        for (int ci = 0; ci < NCH; ci++) {
            int s0 = ci * 64;
            if (ci + 1 < NCH) cp_wait<1>(); else cp_wait<0>();
            __syncthreads();
            if (ci + 2 < NCH) issueKV(ci + 2);
            cp_commit();

            const uint32_t sK0 = smem_u32(sKb + (ci % 3) * 4608);
            const uint32_t sV0 = smem_u32(sVb + (ci % 3) * 4608);

            float sc[8][4];
            #pragma unroll
            for (int t = 0; t < 8; t++)
                #pragma unroll
                for (int j = 0; j < 4; j++) sc[t][j] = 0.0f;

            #pragma unroll
            for (int kk = 0; kk < 4; kk++) {
                uint32_t af[4];
                {
                    int row = warp * 16 + (lane & 15);
                    int col = kk * 16 + ((lane >> 4) << 3);
                    ldm4(af, sQ0 + (uint32_t)((row * 72 + col) * 2));
                }
                #pragma unroll
                for (int ib = 0; ib < 4; ib++) {
                    uint32_t r4[4];
                    int g = lane >> 3;
                    int row = ib * 16 + ((g >> 1) << 3) + (lane & 7);
                    int col = kk * 16 + ((g & 1) << 3);
                    ldm4(r4, sK0 + (uint32_t)((row * 72 + col) * 2));
                    uint32_t b0[2] = {r4[0], r4[1]}, b1[2] = {r4[2], r4[3]};
                    mma_bf16(sc[2 * ib], af, b0);
                    mma_bf16(sc[2 * ib + 1], af, b1);
                }
            }

            float cmax[2] = {-1e30f, -1e30f};
            #pragma unroll
            for (int t = 0; t < 8; t++)
                #pragma unroll
                for (int j = 0; j < 4; j++) {
                    int col = s0 + t * 8 + ((lane & 3) << 1) + (j & 1);
                    if (col >= SQ) sc[t][j] = -1e30f;
                    int rr = j >> 1;
                    cmax[rr] = fmaxf(cmax[rr], sc[t][j]);
                }
            #pragma unroll
            for (int rr = 0; rr < 2; rr++) {
                cmax[rr] = fmaxf(cmax[rr], __shfl_xor_sync(0xffffffffu, cmax[rr], 1));
                cmax[rr] = fmaxf(cmax[rr], __shfl_xor_sync(0xffffffffu, cmax[rr], 2));
            }
            float corr[2];
            #pragma unroll
            for (int rr = 0; rr < 2; rr++) {
                float nm = fmaxf(rmax[rr], cmax[rr]);
                corr[rr] = __expf(rmax[rr] - nm);
                rmax[rr] = nm;
            }
            float psum[2] = {0.0f, 0.0f};
            #pragma unroll
            for (int t = 0; t < 8; t++)
                #pragma unroll
                for (int j = 0; j < 4; j++) {
                    int rr = j >> 1;
                    float p = __expf(sc[t][j] - rmax[rr]);
                    sc[t][j] = p;
                    psum[rr] += p;
                }
            #pragma unroll
            for (int rr = 0; rr < 2; rr++) {
                psum[rr] += __shfl_xor_sync(0xffffffffu, psum[rr], 1);
                psum[rr] += __shfl_xor_sync(0xffffffffu, psum[rr], 2);
                rsum[rr] = rsum[rr] * corr[rr] + psum[rr];
            }
            #pragma unroll
            for (int t = 0; t < 8; t++)
                #pragma unroll
                for (int j = 0; j < 4; j++) oacc[t][j] *= corr[j >> 1];

            #pragma unroll
            for (int kk = 0; kk < 4; kk++) {
                uint32_t ap[4];
                ap[0] = packbf(sc[2 * kk][0], sc[2 * kk][1]);
                ap[1] = packbf(sc[2 * kk][2], sc[2 * kk][3]);
                ap[2] = packbf(sc[2 * kk + 1][0], sc[2 * kk + 1][1]);
                ap[3] = packbf(sc[2 * kk + 1][2], sc[2 * kk + 1][3]);
                #pragma unroll
                for (int ib = 0; ib < 4; ib++) {
                    uint32_t r4[4];
                    int g = lane >> 3;
                    int row = ib * 16 + ((g >> 1) << 3) + (lane & 7);
                    int col = kk * 16 + ((g & 1) << 3);
                    ldm4(r4, sV0 + (uint32_t)((row * 72 + col) * 2));
                    uint32_t b0[2] = {r4[0], r4[1]}, b1[2] = {r4[2], r4[3]};
                    mma_bf16(oacc[2 * ib], ap, b0);
                    mma_bf16(oacc[2 * ib + 1], ap, b1);
                }
            }
        }

        #pragma unroll
        for (int t = 0; t < 8; t++)
            #pragma unroll
            for (int j = 0; j < 4; j++) {
                int r = q0 + warp * 16 + (lane >> 2) + ((j >> 1) << 3);
                int c = h * HDQ + t * 8 + ((lane & 3) << 1) + (j & 1);
                O[(size_t)(b * NQ + r) * CQ + c] = __float2bfloat16(oacc[t][j] / rsum[j >> 1]);
            }
        __syncthreads();
    }
#endif
}

// ---------------- launch ----------------
extern "C" void kernel_launch(void* const* d_in, const int* in_sizes, int n_in,
                              void* d_out, int out_size) {
    const float* x    = (const float*)d_in[0];
    const float* ins  = (const float*)d_in[1];
    const float* n1w  = (const float*)d_in[2];
    const float* n1b  = (const float*)d_in[3];
    const float* qkvw = (const float*)d_in[4];
    const float* qb   = (const float*)d_in[5];
    const float* vb   = (const float*)d_in[6];
    const float* pw   = (const float*)d_in[7];
    const float* pb   = (const float*)d_in[8];
    const float* g1   = (const float*)d_in[9];
    const float* g2   = (const float*)d_in[10];
    const float* n2w  = (const float*)d_in[11];
    const float* n2b  = (const float*)d_in[12];
    const float* f1w  = (const float*)d_in[13];
    const float* f1b  = (const float*)d_in[14];
    const float* f2w  = (const float*)d_in[15];
    const float* f2bv = (const float*)d_in[16];
    const float* p1w  = (const float*)d_in[17];
    const float* p1b  = (const float*)d_in[18];
    const float* p2w  = (const float*)d_in[19];
    const float* p2b  = (const float*)d_in[20];
    const float* gate = (const float*)d_in[21];
    const float* ilw  = (const float*)d_in[22];
    const float* ilb  = (const float*)d_in[23];
    const float* l1w  = (const float*)d_in[24];
    const float* l1b  = (const float*)d_in[25];
    const float* l2w  = (const float*)d_in[26];
    const float* l2b  = (const float*)d_in[27];
    float* out = (float*)d_out;

    bf16 *w_qkv, *w_proj, *w_fc1, *w_fc2, *w_l1, *w_l2;
    bf16 *insln, *hir, *cat, *qB, *kB, *vB, *obuf, *ybuf, *h1;
    float *x1, *qkvbias, *fb1c, *cb;
    cudaGetSymbolAddress((void**)&w_qkv,  g_wqkv);
    cudaGetSymbolAddress((void**)&w_proj, g_wproj);
    cudaGetSymbolAddress((void**)&w_fc1,  g_wfc1);
    cudaGetSymbolAddress((void**)&w_fc2,  g_wfc2);
    cudaGetSymbolAddress((void**)&w_l1,   g_wl1);
    cudaGetSymbolAddress((void**)&w_l2,   g_wl2);
    cudaGetSymbolAddress((void**)&insln,  g_insln);
    cudaGetSymbolAddress((void**)&hir,    g_hir);
    cudaGetSymbolAddress((void**)&cat,    g_cat);
    cudaGetSymbolAddress((void**)&qB,     g_qbuf);
    cudaGetSymbolAddress((void**)&kB,     g_kbuf);
    cudaGetSymbolAddress((void**)&vB,     g_vbuf);
    cudaGetSymbolAddress((void**)&obuf,   g_obuf);
    cudaGetSymbolAddress((void**)&ybuf,   g_ybuf);
    cudaGetSymbolAddress((void**)&h1,     g_h1);
    cudaGetSymbolAddress((void**)&x1,     g_x1);
    cudaGetSymbolAddress((void**)&qkvbias, g_qkvbias);
    cudaGetSymbolAddress((void**)&fb1c,   g_fb1c);
    cudaGetSymbolAddress((void**)&cb,     g_cb);

    cudaFuncSetAttribute(big_gemm_kernel<0>, cudaFuncAttributeMaxDynamicSharedMemorySize, BG_SMEM);
    cudaFuncSetAttribute(big_gemm_kernel<1>, cudaFuncAttributeMaxDynamicSharedMemorySize, BG_SMEM);
    cudaFuncSetAttribute(big_gemm_kernel<2>, cudaFuncAttributeMaxDynamicSharedMemorySize, BG_SMEM);
    cudaFuncSetAttribute(big_gemm_kernel<3>, cudaFuncAttributeMaxDynamicSharedMemorySize, BG_SMEM);
    cudaFuncSetAttribute(big_gemm_kernel<4>, cudaFuncAttributeMaxDynamicSharedMemorySize, BG_SMEM);
    cudaFuncSetAttribute(flash_kernel, cudaFuncAttributeMaxDynamicSharedMemorySize, FL_SMEM);

    // 1) fused front-end
    {
        MegaArgs a;
        a.qkvw = qkvw; a.pw = pw; a.l1w = l1w; a.l2w = l2w;
        a.f1w = f1w; a.p1w = p1w; a.f2w = f2w; a.p2w = p2w;
        a.qb = qb; a.vb = vb; a.f1b = f1b; a.p1b = p1b;
        a.f2b = f2bv; a.p2b = p2b; a.g2 = g2; a.gate = gate;
        a.wqkv = w_qkv; a.wproj = w_proj; a.wl1 = w_l1; a.wl2 = w_l2;
        a.wfc1 = w_fc1; a.wfc2 = w_fc2;
        a.qkvbias = qkvbias; a.fb1c = fb1c; a.cb = cb;
        a.ins = ins; a.ilw = ilw; a.ilb = ilb;
        a.x = x; a.n1w = n1w; a.n1b = n1b;
        a.insln = insln; a.cat = cat;
        mega_pre_kernel<<<MEGA_BLOCKS, 256>>>(a);
    }

    // 2) instruct l1 (gelu)
    {
        EpiParams ep; ep.bias = l1b; ep.outb = hir;
        big_gemm_kernel<0><<<dim3(CQ / 128, (BQ * IQ + 127) / 128), 256, BG_SMEM>>>(
            insln, w_l1, BQ * IQ, CQ, IDQ, ep);
    }
    // 3) instruct l2 -> cat rows [0, I)
    {
        EpiParams ep; ep.bias = l2b; ep.outb = cat;
        big_gemm_kernel<1><<<dim3(CQ / 128, (BQ * IQ + 127) / 128), 256, BG_SMEM>>>(
            hir, w_l2, BQ * IQ, CQ, CQ, ep);
    }

    // 4) qkv projection (v written transposed)
    {
        EpiParams ep; ep.bias = qkvbias; ep.q = qB; ep.k = kB; ep.v = vB;
        big_gemm_kernel<2><<<dim3(3 * CQ / 128, (BQ * SQ + 127) / 128), 256, BG_SMEM>>>(
            cat, w_qkv, BQ * SQ, 3 * CQ, CQ, ep);
    }

    // 5) attention (tcgen05 flash)
    flash_kernel<<<dim3(NQ / 128, HQ, BQ), 128, FL_SMEM>>>(qB, kB, vB, obuf);

    // 6) proj + LayerScale residual -> x1
    {
        EpiParams ep; ep.bias = pb; ep.outf = x1; ep.resid = x; ep.gvec = g1;
        big_gemm_kernel<3><<<dim3(CQ / 128, BQ * NQ / 128), 256, BG_SMEM>>>(
            obuf, w_proj, BQ * NQ, CQ, CQ, ep);
    }

    // 7) y = LN(x1)
    ln_kernel<<<BQ * NQ, 256>>>(x1, n2w, n2b, ybuf, CQ);

    // 8) combined mlp up: h1 = gelu(y @ [fc1;pfc1]^T + [f1b;p1b])
    {
        EpiParams ep; ep.bias = fb1c; ep.outb = h1;
        big_gemm_kernel<0><<<dim3(2 * HIDQ / 128, BQ * NQ / 128), 256, BG_SMEM>>>(
            ybuf, w_fc1, BQ * NQ, 2 * HIDQ, CQ, ep);
    }
    // 9) combined mlp down: out = x1 + h1 @ [g2*fc2 | gate*pfc2]^T + cb
    {
        EpiParams ep; ep.bias = cb; ep.outf = out; ep.resid = x1;
        big_gemm_kernel<4><<<dim3(CQ / 128, BQ * NQ / 128), 256, BG_SMEM>>>(
            h1, w_fc2, BQ * NQ, CQ, 2 * HIDQ, ep);
    }
}

// round 14
// speedup vs baseline: 1.2168x; 1.0172x over previous
#include <cuda_runtime.h>
#include <cuda_bf16.h>
#include <cstdint>
#include <math.h>

typedef __nv_bfloat16 bf16;

#define BQ 4
#define NQ 1024
#define CQ 1024
#define HQ 16
#define IQ 77
#define IDQ 768
#define HDQ 64
#define HIDQ 4096
#define SQ (IQ + NQ)   // 1101
#define SQP 1152       // padded KV length for transposed V

// ---------------- device scratch ----------------
// big-GEMM weights: tiled [NT=N/128][KC=K/64] blocks of 128x64 bf16 (16KB), SW128-swizzled
__device__ __align__(16) bf16 g_wqkv [3*CQ*CQ];
__device__ __align__(16) bf16 g_wproj[CQ*CQ];
__device__ __align__(16) bf16 g_wfc1 [2*HIDQ*CQ];   // [fc1 ; pfc1] stacked on N
__device__ __align__(16) bf16 g_wfc2 [CQ*2*HIDQ];   // [g2*fc2 | gate*pfc2] on K
__device__ __align__(16) bf16 g_wl1  [CQ*IDQ];
__device__ __align__(16) bf16 g_wl2  [CQ*CQ];

__device__ __align__(16) bf16 g_insln[BQ*IQ*IDQ];
__device__ __align__(16) bf16 g_hir  [BQ*IQ*CQ];
__device__ __align__(16) bf16 g_cat  [BQ*SQ*CQ];
__device__ __align__(16) bf16 g_qbuf [BQ*HQ*SQ*HDQ];
__device__ __align__(16) bf16 g_kbuf [BQ*HQ*SQ*HDQ];
__device__ __align__(16) bf16 g_vbuf [BQ*HQ*HDQ*SQP];   // TRANSPOSED [B,H,HD,SQP]
__device__ __align__(16) bf16 g_obuf [BQ*NQ*CQ];
__device__ __align__(16) bf16 g_ybuf [BQ*NQ*CQ];
__device__ __align__(16) bf16 g_h1   [BQ*NQ*2*HIDQ];
__device__ __align__(16) float g_x1  [BQ*NQ*CQ];
__device__ float g_qkvbias[3*CQ];
__device__ float g_fb1c[2*HIDQ];
__device__ float g_cb[CQ];

// ---------------- helpers ----------------
__device__ __forceinline__ uint32_t smem_u32(const void* p) {
    return (uint32_t)__cvta_generic_to_shared(p);
}
__device__ __forceinline__ void cpa16(uint32_t s, const void* g, bool p) {
    int sz = p ? 16 : 0;
    asm volatile("cp.async.cg.shared.global [%0], [%1], 16, %2;"
                 :: "r"(s), "l"(g), "r"(sz));
}
__device__ __forceinline__ void cp_commit() { asm volatile("cp.async.commit_group;"); }
template <int N_> __device__ __forceinline__ void cp_wait() {
    asm volatile("cp.async.wait_group %0;" :: "n"(N_));
}
__device__ __forceinline__ void ldm4(uint32_t* r, uint32_t a) {
    asm volatile("ldmatrix.sync.aligned.m8n8.x4.shared.b16 {%0,%1,%2,%3}, [%4];"
        : "=r"(r[0]), "=r"(r[1]), "=r"(r[2]), "=r"(r[3]) : "r"(a));
}
__device__ __forceinline__ void mma_bf16(float* d, const uint32_t* a, const uint32_t* b) {
    asm volatile("mma.sync.aligned.m16n8k16.row.col.f32.bf16.bf16.f32 "
        "{%0,%1,%2,%3}, {%4,%5,%6,%7}, {%8,%9}, {%0,%1,%2,%3};"
        : "+f"(d[0]), "+f"(d[1]), "+f"(d[2]), "+f"(d[3])
        : "r"(a[0]), "r"(a[1]), "r"(a[2]), "r"(a[3]), "r"(b[0]), "r"(b[1]));
}
__device__ __forceinline__ float gelu_exact(float x) {
    return 0.5f * x * (1.0f + erff(x * 0.70710678118654752f));
}
__device__ __forceinline__ uint32_t packbf(float a, float b) {
    __nv_bfloat162 t = __floats2bfloat162_rn(a, b);
    return *reinterpret_cast<uint32_t*>(&t);
}

// tiled weight addressing: element (n, k) of an [N][K] weight; 128x64 blocks, KC = K/64
__device__ __forceinline__ size_t wt_byteoff(int KC, int n, int k) {
    int nt = n >> 7, rl = n & 127, kc = k >> 6, cl = k & 63;
    size_t blk = ((size_t)(nt * KC + kc)) * 16384;
    uint32_t off = (uint32_t)(rl * 128 + cl * 2);
    uint32_t sw = off ^ ((off >> 3) & 0x70);
    return blk + sw;
}

#if defined(__CUDA_ARCH_FEAT_SM103_ALL)
#define HAS_TG 1
__device__ __forceinline__ uint32_t elect1() {
    uint32_t p;
    asm volatile("{\n\t.reg .pred p;\n\telect.sync _|p, 0xFFFFFFFF;\n\tselp.b32 %0, 1, 0, p;\n\t}"
        : "=r"(p));
    return p;
}
__device__ __forceinline__ void mbar_init(uint32_t a, uint32_t cnt) {
    asm volatile("mbarrier.init.shared.b64 [%0], %1;" :: "r"(a), "r"(cnt) : "memory");
}
__device__ __forceinline__ void mbar_wait(uint32_t a, int parity) {
    asm volatile("{\n\t.reg .pred P;\n\tWL%=:\n\t"
        "mbarrier.try_wait.parity.shared::cta.b64 P, [%0], %1;\n\t"
        "@!P bra WL%=;\n\t}" :: "r"(a), "r"(parity) : "memory");
}
__device__ __forceinline__ void mbar_arrive(uint32_t a) {
    asm volatile("mbarrier.arrive.shared.b64 _, [%0];" :: "r"(a) : "memory");
}
__device__ __forceinline__ void cpa_mbar_arrive_noinc(uint32_t a) {
    asm volatile("cp.async.mbarrier.arrive.noinc.shared::cta.b64 [%0];" :: "r"(a) : "memory");
}
__device__ __forceinline__ void mbar_expect_tx(uint32_t a, uint32_t bytes) {
    asm volatile("mbarrier.arrive.expect_tx.shared.b64 _, [%0], %1;"
        :: "r"(a), "r"(bytes) : "memory");
}
__device__ __forceinline__ void bulk_ld(uint32_t dst, const void* src, uint32_t bytes, uint32_t mbar) {
    asm volatile("cp.async.bulk.shared::cluster.global.mbarrier::complete_tx::bytes "
        "[%0], [%1], %2, [%3];"
        :: "r"(dst), "l"(src), "r"(bytes), "r"(mbar) : "memory");
}
__device__ __forceinline__ void tg_mma_f16_ss(uint32_t d, uint64_t ad, uint64_t bd,
                                              uint32_t idesc, bool en) {
    uint32_t e = en ? 1u : 0u;
    asm volatile("{\n\t.reg .pred p;\n\tsetp.ne.u32 p, %4, 0;\n\t"
        "tcgen05.mma.cta_group::1.kind::f16 [%0], %1, %2, %3, {%5,%5,%5,%5}, p;\n\t}"
        :: "r"(d), "l"(ad), "l"(bd), "r"(idesc), "r"(e), "r"(0u) : "memory");
}
__device__ __forceinline__ void tg_commit(uint32_t mbar) {
    asm volatile("tcgen05.commit.cta_group::1.mbarrier::arrive::one.shared::cluster.b64 [%0];"
        :: "r"(mbar) : "memory");
}
__device__ __forceinline__ void tg_ld32(uint32_t* r, uint32_t a) {
    asm volatile("tcgen05.ld.sync.aligned.32x32b.x32.b32 "
        "{%0,%1,%2,%3,%4,%5,%6,%7,%8,%9,%10,%11,%12,%13,%14,%15,"
        "%16,%17,%18,%19,%20,%21,%22,%23,%24,%25,%26,%27,%28,%29,%30,%31}, [%32];"
        : "=r"(r[0]),"=r"(r[1]),"=r"(r[2]),"=r"(r[3]),"=r"(r[4]),"=r"(r[5]),"=r"(r[6]),"=r"(r[7]),
          "=r"(r[8]),"=r"(r[9]),"=r"(r[10]),"=r"(r[11]),"=r"(r[12]),"=r"(r[13]),"=r"(r[14]),"=r"(r[15]),
          "=r"(r[16]),"=r"(r[17]),"=r"(r[18]),"=r"(r[19]),"=r"(r[20]),"=r"(r[21]),"=r"(r[22]),"=r"(r[23]),
          "=r"(r[24]),"=r"(r[25]),"=r"(r[26]),"=r"(r[27]),"=r"(r[28]),"=r"(r[29]),"=r"(r[30]),"=r"(r[31])
        : "r"(a));
}
#define TG_WAIT_LD()  asm volatile("tcgen05.wait::ld.sync.aligned;" ::: "memory")
#define TG_FENCE_AFTER() asm volatile("tcgen05.fence::after_thread_sync;" ::: "memory")
#define TG_ALLOC(sm, n) asm volatile("tcgen05.alloc.cta_group::1.sync.aligned.shared::cta.b32 [%0], %1;" :: "r"(sm), "r"((uint32_t)(n)) : "memory")
#define TG_DEALLOC(t, n) asm volatile("tcgen05.dealloc.cta_group::1.sync.aligned.b32 %0, %1;" :: "r"(t), "r"((uint32_t)(n)))
#define TG_RELINQ() asm volatile("tcgen05.relinquish_alloc_permit.cta_group::1.sync.aligned;")

static __device__ __forceinline__ uint64_t mk_desc(uint32_t addr) {
    return ((uint64_t)2 << 61) | ((uint64_t)1 << 46) | ((uint64_t)64 << 32) |
           ((uint64_t)1 << 16) | (uint64_t)((addr >> 4) & 0x3FFF);
}
#endif

// ---------------- fused front-end: tiled weight cvt + bias prep + LN(ins) + LN(x) ----
struct MegaArgs {
    const float *qkvw, *pw, *l1w, *l2w, *f1w, *p1w, *f2w, *p2w;
    const float *qb, *vb, *f1b, *p1b, *f2b, *p2b, *g2, *gate;
    bf16 *wqkv, *wproj, *wl1, *wl2, *wfc1, *wfc2;
    float *qkvbias, *fb1c, *cb;
    const float *ins, *ilw, *ilb, *x, *n1w, *n1b;
    bf16 *insln, *cat;
};

#define CVT_V4_BLOCKS 22272
#define CVT_MISC_BLOCKS 48
#define LNI_BLOCKS (BQ * IQ)     // 308
#define LNX_BLOCKS (BQ * NQ)     // 4096
#define MEGA_BLOCKS (CVT_V4_BLOCKS + CVT_MISC_BLOCKS + LNI_BLOCKS + LNX_BLOCKS)

__device__ __forceinline__ void cvt_tiled4(const float* row, bf16* dst, int KC,
                                           int n, int k, float s) {
    float4 v = *(const float4*)(row + k);
    uint2 o;
    o.x = packbf(v.x * s, v.y * s);
    o.y = packbf(v.z * s, v.w * s);
    *(uint2*)((char*)dst + wt_byteoff(KC, n, k)) = o;
}

__device__ void ln_row(const float* __restrict__ p, const float* __restrict__ w,
                       const float* __restrict__ bia, bf16* __restrict__ op,
                       int D, float* sm) {
    int tid = threadIdx.x;
    float s = 0.0f, s2 = 0.0f;
    for (int i = tid; i < D; i += 256) { float v = p[i]; s += v; s2 += v * v; }
    #pragma unroll
    for (int o = 16; o; o >>= 1) {
        s  += __shfl_xor_sync(0xffffffffu, s, o);
        s2 += __shfl_xor_sync(0xffffffffu, s2, o);
    }
    int warp = tid >> 5, lane = tid & 31;
    if (lane == 0) { sm[warp] = s; sm[warp + 8] = s2; }
    __syncthreads();
    s = 0.0f; s2 = 0.0f;
    #pragma unroll
    for (int i = 0; i < 8; i++) { s += sm[i]; s2 += sm[i + 8]; }
    float m = s / D;
    float var = s2 / D - m * m;
    float inv = rsqrtf(var + 1e-5f);
    for (int i = tid; i < D; i += 256)
        op[i] = __float2bfloat16((p[i] - m) * inv * w[i] + bia[i]);
}

__global__ void mega_pre_kernel(MegaArgs a) {
    __shared__ float sm[16];
    int bid = blockIdx.x;
    int tid = threadIdx.x;
    if (bid < CVT_V4_BLOCKS) {
        int i = bid * 256 + tid;
        if (i < 786432) {                       // wqkv 3072x1024, KC=16
            int n = i >> 8, k = (i & 255) * 4;
            cvt_tiled4(a.qkvw + (size_t)n * CQ, a.wqkv, 16, n, k, 1.0f);
        } else if (i < 1048576) {               // wproj 1024x1024, KC=16
            int j = i - 786432;
            int n = j >> 8, k = (j & 255) * 4;
            cvt_tiled4(a.pw + (size_t)n * CQ, a.wproj, 16, n, k, 1.0f);
        } else if (i < 1245184) {               // wl1 1024x768, KC=12
            int j = i - 1048576;
            int n = j / 192, k = (j % 192) * 4;
            cvt_tiled4(a.l1w + (size_t)n * IDQ, a.wl1, 12, n, k, 1.0f);
        } else if (i < 1507328) {               // wl2 1024x1024, KC=16
            int j = i - 1245184;
            int n = j >> 8, k = (j & 255) * 4;
            cvt_tiled4(a.l2w + (size_t)n * CQ, a.wl2, 16, n, k, 1.0f);
        } else if (i < 2555904) {               // fc1 rows [0,4096), KC=16
            int j = i - 1507328;
            int n = j >> 8, k = (j & 255) * 4;
            cvt_tiled4(a.f1w + (size_t)n * CQ, a.wfc1, 16, n, k, 1.0f);
        } else if (i < 3604480) {               // pfc1 rows [4096,8192), KC=16
            int j = i - 2555904;
            int n = j >> 8, k = (j & 255) * 4;
            cvt_tiled4(a.p1w + (size_t)n * CQ, a.wfc1, 16, n + HIDQ, k, 1.0f);
        } else if (i < 4653056) {               // g2*fc2 cols [0,4096), KC=128
            int j = i - 3604480;
            int n = j >> 10, k = (j & 1023) * 4;
            float s = a.g2[n];
            float4 v = *(const float4*)(a.f2w + (size_t)n * HIDQ + k);
            uint2 o;
            o.x = packbf(v.x * s, v.y * s);
            o.y = packbf(v.z * s, v.w * s);
            *(uint2*)((char*)a.wfc2 + wt_byteoff(128, n, k)) = o;
        } else {                                // gate*pfc2 cols [4096,8192), KC=128
            int j = i - 4653056;
            int n = j >> 10, kk = (j & 1023) * 4;
            float s = a.gate[0];
            float4 v = *(const float4*)(a.p2w + (size_t)n * HIDQ + kk);
            uint2 o;
            o.x = packbf(v.x * s, v.y * s);
            o.y = packbf(v.z * s, v.w * s);
            *(uint2*)((char*)a.wfc2 + wt_byteoff(128, n, kk + HIDQ)) = o;
        }
    } else if (bid < CVT_V4_BLOCKS + CVT_MISC_BLOCKS) {
        int t = (bid - CVT_V4_BLOCKS) * 256 + tid;
        if (t < 3072) {
            float v = 0.0f;
            if (t < CQ) v = a.qb[t];
            else if (t >= 2 * CQ) v = a.vb[t - 2 * CQ];
            a.qkvbias[t] = v;
        } else if (t < 11264) {
            int j = t - 3072;
            a.fb1c[j] = (j < HIDQ) ? a.f1b[j] : a.p1b[j - HIDQ];
        } else {
            int j = t - 11264;
            a.cb[j] = a.g2[j] * a.f2b[j] + a.gate[0] * a.p2b[j];
        }
    } else if (bid < CVT_V4_BLOCKS + CVT_MISC_BLOCKS + LNI_BLOCKS) {
        int row = bid - (CVT_V4_BLOCKS + CVT_MISC_BLOCKS);
        ln_row(a.ins + (size_t)row * IDQ, a.ilw, a.ilb,
               a.insln + (size_t)row * IDQ, IDQ, sm);
    } else {
        int row = bid - (CVT_V4_BLOCKS + CVT_MISC_BLOCKS + LNI_BLOCKS);
        int bb = row >> 10, n = row & 1023;
        ln_row(a.x + (size_t)row * CQ, a.n1w, a.n1b,
               a.cat + (size_t)(bb * SQ + IQ + n) * CQ, CQ, sm);
    }
}

// ---------------- LayerNorm (standalone — LN2 only) ----------------
__global__ void ln_kernel(const float* __restrict__ in, const float* __restrict__ w,
                          const float* __restrict__ bia, bf16* __restrict__ out, int D) {
    __shared__ float sm[16];
    int row = blockIdx.x;
    ln_row(in + (size_t)row * D, w, bia, out + (size_t)row * D, D, sm);
}

// ---------------- epilogue params ----------------
struct EpiParams {
    const float* bias  = nullptr;
    bf16*  outb        = nullptr;
    float* outf        = nullptr;
    const float* resid = nullptr;
    const float* gvec  = nullptr;
    bf16* q = nullptr; bf16* k = nullptr; bf16* v = nullptr;
};

// ---------------- big GEMM: warp-specialized tcgen05 pipeline ----------------
// 128x128 tile, BK=64, 3 stages. Warps 0-3: A cp.async producers (async arrivals
// via cp.async.mbarrier.arrive.NOINC) + tid0 B bulk; warp 4: MMA issue.
// full[s] count=129 (128 noinc A-arrivals + expect_tx); done[s] count=1 (commit).
// MODE 0: outb = gelu(acc+bias) ; 1: cat scatter ; 2: qkv split (V transposed) ;
// MODE 3: outf = resid + gvec*acc+bias ; 4: outf = resid + acc + bias
#define BG_SMEM 100352

template <int MODE>
__global__ __launch_bounds__(256, 2)
void big_gemm_kernel(const bf16* __restrict__ A, const bf16* __restrict__ W,
                     int M, int N, int K, EpiParams ep) {
#if defined(__CUDA_ARCH_FEAT_SM103_ALL)
    extern __shared__ char dsm[];
    char* base = (char*)(((uintptr_t)dsm + 1023) & ~(uintptr_t)1023);
    const uint32_t sb = smem_u32(base);
    const int tid = threadIdx.x, warp = tid >> 5;
    const int mbase = blockIdx.y * 128, nbase = blockIdx.x * 128;
    const int KC = K >> 6;
    const int NK = KC;

    if (warp == 0) { TG_ALLOC(sb, 128); }
    if (tid == 0) {
        mbar_init(sb + 8, 129);   // full 0..2
        mbar_init(sb + 16, 129);
        mbar_init(sb + 24, 129);
        mbar_init(sb + 32, 1);    // done 0..2
        mbar_init(sb + 40, 1);
        mbar_init(sb + 48, 1);
    }
    __syncthreads();
    uint32_t tmem;
    asm volatile("ld.shared.b32 %0, [%1];" : "=r"(tmem) : "r"(sb));
    if (warp == 0) TG_RELINQ();

    auto stA = [&](int s) -> uint32_t { return sb + 2048 + s * 32768; };
    auto fullb = [&](int s) -> uint32_t { return sb + 8 + 8 * s; };
    auto doneb = [&](int s) -> uint32_t { return sb + 32 + 8 * s; };

    if (tid < 128) {
        // -------- producers (warps 0-3): never block on memory --------
        for (int kt = 0; kt < NK; kt++) {
            int s = kt % 3;
            if (kt >= 3) mbar_wait(doneb(s), ((kt - 3) / 3) & 1);
            uint32_t a0 = stA(s);
            int k0 = kt << 6;
            #pragma unroll
            for (int i = 0; i < 8; i++) {
                int idx = tid + i * 128;
                int r = idx >> 3, cch = idx & 7;
                uint32_t off = (uint32_t)(r * 128 + cch * 16);
                uint32_t sw = off ^ ((off >> 3) & 0x70);
                bool pa = (mbase + r) < M;
                const bf16* ga = pa ? (A + (size_t)(mbase + r) * K + k0 + cch * 8) : A;
                cpa16(a0 + sw, ga, pa);
            }
            cp_commit();
            if (tid == 0) {
                mbar_expect_tx(fullb(s), 16384);
                bulk_ld(a0 + 16384,
                        (const char*)W + ((size_t)(blockIdx.x * KC + kt)) * 16384,
                        16384, fullb(s));
            }
            // NOINC async arrival: fires when this thread's prior cp.asyncs complete
            cpa_mbar_arrive_noinc(fullb(s));
        }
    } else if (warp == 4) {
        // -------- MMA consumer --------
        const uint32_t lead = elect1();
        const uint32_t idesc = (1u << 4) | (1u << 7) | (1u << 10) | (16u << 17) | (8u << 24);
        for (int kt = 0; kt < NK; kt++) {
            int s = kt % 3;
            mbar_wait(fullb(s), (kt / 3) & 1);
            asm volatile("fence.proxy.async.shared::cta;" ::: "memory");
            if (lead) {
                uint64_t ad = mk_desc(stA(s));
                uint64_t bd = mk_desc(stA(s) + 16384);
                #pragma unroll
                for (int stp = 0; stp < 4; stp++)
                    tg_mma_f16_ss(tmem, ad + stp * 2, bd + stp * 2, idesc,
                                  (kt > 0) || (stp > 0));
                tg_commit(doneb(s));
            }
        }
    }

    // all threads: wait for the final chunk's MMA completion
    {
        int sl = (NK - 1) % 3;
        int cnt = (NK - 1 - sl) / 3 + 1;
        mbar_wait(doneb(sl), (cnt - 1) & 1);
    }
    TG_FENCE_AFTER();
    __syncthreads();

    if (tid < 128) {
        const int grow = mbase + tid;
        #pragma unroll
        for (int cc = 0; cc < 4; cc++) {
            uint32_t regs[32];
            tg_ld32(regs, tmem + cc * 32);
            TG_WAIT_LD();
            if (grow < M) {
                const int c0 = nbase + cc * 32;
                float vals[32];
                #pragma unroll
                for (int c = 0; c < 32; c++)
                    vals[c] = __uint_as_float(regs[c]) + ep.bias[c0 + c];

                if (MODE == 0) {
                    uint32_t pk[16];
                    #pragma unroll
                    for (int c = 0; c < 16; c++)
                        pk[c] = packbf(gelu_exact(vals[2*c]), gelu_exact(vals[2*c+1]));
                    uint4* dst = (uint4*)(ep.outb + (size_t)grow * N + c0);
                    #pragma unroll
                    for (int q = 0; q < 4; q++)
                        dst[q] = make_uint4(pk[4*q], pk[4*q+1], pk[4*q+2], pk[4*q+3]);
                } else if (MODE == 1) {
                    int bb = grow / IQ, ii = grow % IQ;
                    uint32_t pk[16];
                    #pragma unroll
                    for (int c = 0; c < 16; c++)
                        pk[c] = packbf(vals[2*c], vals[2*c+1]);
                    uint4* dst = (uint4*)(ep.outb + (size_t)(bb * SQ + ii) * CQ + c0);
                    #pragma unroll
                    for (int q = 0; q < 4; q++)
                        dst[q] = make_uint4(pk[4*q], pk[4*q+1], pk[4*q+2], pk[4*q+3]);
                } else if (MODE == 2) {
                    int bb = grow / SQ, s = grow % SQ;
                    int sec = c0 >> 10, hh = (c0 & 1023) >> 6, d0 = c0 & 63;
                    if (sec == 2) {
                        bf16* vt = ep.v + (size_t)(bb * HQ + hh) * HDQ * SQP;
                        #pragma unroll
                        for (int c = 0; c < 32; c++)
                            vt[(size_t)(d0 + c) * SQP + s] = __float2bfloat16(vals[c]);
                    } else {
                        size_t off = ((size_t)(bb * HQ + hh) * SQ + s) * HDQ + d0;
                        bf16* dstp; float scl = 1.0f;
                        if (sec == 0) { dstp = ep.q + off; scl = 0.125f; }
                        else          { dstp = ep.k + off; }
                        uint32_t pk[16];
                        #pragma unroll
                        for (int c = 0; c < 16; c++)
                            pk[c] = packbf(vals[2*c] * scl, vals[2*c+1] * scl);
                        uint4* dst = (uint4*)dstp;
                        #pragma unroll
                        for (int q = 0; q < 4; q++)
                            dst[q] = make_uint4(pk[4*q], pk[4*q+1], pk[4*q+2], pk[4*q+3]);
                    }
                } else if (MODE == 3) {
                    const float4* rs = (const float4*)(ep.resid + (size_t)grow * CQ + c0);
                    float4* dst = (float4*)(ep.outf + (size_t)grow * CQ + c0);
                    #pragma unroll
                    for (int q = 0; q < 8; q++) {
                        float4 rv = rs[q];
                        float4 o;
                        o.x = rv.x + ep.gvec[c0 + 4*q + 0] * vals[4*q + 0];
                        o.y = rv.y + ep.gvec[c0 + 4*q + 1] * vals[4*q + 1];
                        o.z = rv.z + ep.gvec[c0 + 4*q + 2] * vals[4*q + 2];
                        o.w = rv.w + ep.gvec[c0 + 4*q + 3] * vals[4*q + 3];
                        dst[q] = o;
                    }
                } else {
                    const float4* rs = (const float4*)(ep.resid + (size_t)grow * CQ + c0);
                    float4* dst = (float4*)(ep.outf + (size_t)grow * CQ + c0);
                    #pragma unroll
                    for (int q = 0; q < 8; q++) {
                        float4 rv = rs[q];
                        float4 o;
                        o.x = rv.x + vals[4*q + 0];
                        o.y = rv.y + vals[4*q + 1];
                        o.z = rv.z + vals[4*q + 2];
                        o.w = rv.w + vals[4*q + 3];
                        dst[q] = o;
                    }
                }
            }
        }
    }
    __syncthreads();
    if (warp == 0) TG_DEALLOC(tmem, 128);
#else
    // ======== mma.sync fallback (tiled B addressing) ========
    extern __shared__ bf16 smem[];
    bf16* sA = smem;
    bf16* sB = smem + 3 * 5120;
    const int tid  = threadIdx.x;
    const int lane = tid & 31, warp = tid >> 5;
    const int wm = warp & 1, wn = warp >> 1;
    const int mbase = blockIdx.y * 128, nbase = blockIdx.x * 128;
    const int KC = K >> 6;
    const int lr = tid >> 2, lc = (tid & 3) * 8;

    float acc[4][4][4];
    #pragma unroll
    for (int a = 0; a < 4; a++)
        #pragma unroll
        for (int b = 0; b < 4; b++)
            #pragma unroll
            for (int c = 0; c < 4; c++) acc[a][b][c] = 0.0f;

    const int NK = K >> 5;

    auto baddr = [&](int n, int k) -> const bf16* {
        return (const bf16*)((const char*)W + wt_byteoff(KC, n, k));
    };
    auto issue = [&](int kt) {
        int k0 = kt << 5;
        int st = kt % 3;
        bf16* dA = sA + st * 5120;
        bf16* dB = sB + st * 5120;
        bool p1 = (mbase + lr) < M;
        bool p2 = (mbase + lr + 64) < M;
        const bf16* ga1 = p1 ? (A + (size_t)(mbase + lr) * K + k0 + lc) : A;
        const bf16* ga2 = p2 ? (A + (size_t)(mbase + lr + 64) * K + k0 + lc) : A;
        cpa16(smem_u32(dA + lr * 40 + lc), ga1, p1);
        cpa16(smem_u32(dA + (lr + 64) * 40 + lc), ga2, p2);
        cpa16(smem_u32(dB + lr * 40 + lc), baddr(nbase + lr, k0 + lc), true);
        cpa16(smem_u32(dB + (lr + 64) * 40 + lc), baddr(nbase + lr + 64, k0 + lc), true);
    };

    issue(0); cp_commit();
    issue(1); cp_commit();

    for (int kt = 0; kt < NK; kt++) {
        if (kt + 1 < NK) cp_wait<1>(); else cp_wait<0>();
        __syncthreads();
        if (kt + 2 < NK) issue(kt + 2);
        cp_commit();

        const int st = kt % 3;
        const uint32_t a0 = smem_u32(sA + st * 5120);
        const uint32_t b0 = smem_u32(sB + st * 5120);
        #pragma unroll
        for (int ks = 0; ks < 2; ks++) {
            int kc = ks * 16;
            uint32_t af[4][4];
            #pragma unroll
            for (int im = 0; im < 4; im++) {
                int row = wm * 64 + im * 16 + (lane & 15);
                int col = kc + ((lane >> 4) << 3);
                ldm4(af[im], a0 + (uint32_t)((row * 40 + col) * 2));
            }
            uint32_t bfr[4][2];
            #pragma unroll
            for (int ib = 0; ib < 2; ib++) {
                int g = lane >> 3;
                int row = wn * 32 + ib * 16 + ((g >> 1) << 3) + (lane & 7);
                int col = kc + ((g & 1) << 3);
                uint32_t r4[4];
                ldm4(r4, b0 + (uint32_t)((row * 40 + col) * 2));
                bfr[2*ib][0] = r4[0]; bfr[2*ib][1] = r4[1];
                bfr[2*ib+1][0] = r4[2]; bfr[2*ib+1][1] = r4[3];
            }
            #pragma unroll
            for (int im = 0; im < 4; im++)
                #pragma unroll
                for (int in_ = 0; in_ < 4; in_++)
                    mma_bf16(acc[im][in_], af[im], bfr[in_]);
        }
    }

    #pragma unroll
    for (int im = 0; im < 4; im++)
        #pragma unroll
        for (int in_ = 0; in_ < 4; in_++)
            #pragma unroll
            for (int j = 0; j < 4; j++) {
                int r = mbase + wm * 64 + im * 16 + (lane >> 2) + ((j >> 1) << 3);
                int c = nbase + wn * 32 + in_ * 8 + ((lane & 3) << 1) + (j & 1);
                if (r >= M) continue;
                float v = acc[im][in_][j] + ep.bias[c];
                if (MODE == 0) {
                    ep.outb[(size_t)r * N + c] = __float2bfloat16(gelu_exact(v));
                } else if (MODE == 1) {
                    int bb = r / IQ, ii = r % IQ;
                    ep.outb[(size_t)(bb * SQ + ii) * CQ + c] = __float2bfloat16(v);
                } else if (MODE == 2) {
                    int bb = r / SQ, s = r % SQ;
                    int sec = c >> 10, hh = (c & 1023) >> 6, d = c & 63;
                    if (sec == 2) {
                        ep.v[((size_t)(bb * HQ + hh) * HDQ + d) * SQP + s] = __float2bfloat16(v);
                    } else {
                        size_t dst = ((size_t)(bb * HQ + hh) * SQ + s) * HDQ + d;
                        if (sec == 0) ep.q[dst] = __float2bfloat16(v * 0.125f);
                        else          ep.k[dst] = __float2bfloat16(v);
                    }
                } else if (MODE == 3) {
                    ep.outf[(size_t)r * CQ + c] = ep.resid[(size_t)r * CQ + c] + ep.gvec[c] * v;
                } else if (MODE == 4) {
                    ep.outf[(size_t)r * CQ + c] = ep.resid[(size_t)r * CQ + c] + v;
                }
            }
#endif
}

// ---------------- flash attention (round-8 tcgen05 version) ----------------
#define NCH ((SQ + 63) / 64)   // 18
#define FL_SMEM 84992

__global__ __launch_bounds__(128, 2)
void flash_kernel(const bf16* __restrict__ Q, const bf16* __restrict__ K,
                  const bf16* __restrict__ Vt, bf16* __restrict__ O) {
#if defined(__CUDA_ARCH_FEAT_SM103_ALL)
    extern __shared__ char dsm[];
    char* base = (char*)(((uintptr_t)dsm + 1023) & ~(uintptr_t)1023);
    const uint32_t sb = smem_u32(base);
    const int tid = threadIdx.x, warp = tid >> 5;
    const int q0 = blockIdx.x * 128;
    const int h = blockIdx.y, b = blockIdx.z;
    const char* qbase = (const char*)(Q + ((size_t)(b * HQ + h) * SQ + IQ + q0) * HDQ);
    const char* kbase = (const char*)(K + (size_t)(b * HQ + h) * SQ * HDQ);
    const char* vtbase = (const char*)(Vt + (size_t)(b * HQ + h) * HDQ * SQP);

    if (warp == 0) TG_ALLOC(sb, 128);
    if (tid == 0) { mbar_init(sb + 8, 1); mbar_init(sb + 16, 1); }
    __syncthreads();
    uint32_t tmem;
    asm volatile("ld.shared.b32 %0, [%1];" : "=r"(tmem) : "r"(sb));
    if (warp == 0) TG_RELINQ();

    const uint32_t sQ = sb + 1024;
    const uint32_t sP = sQ + 16384;
    const uint32_t sK = sP + 16384;
    const uint32_t sV = sK + 24576;

    #pragma unroll
    for (int i = 0; i < 8; i++) {
        int idx = tid + i * 128;
        int r = idx >> 3, cb = (idx & 7) * 16;
        uint32_t off = (uint32_t)(r * 128 + cb);
        uint32_t sw = off ^ ((off >> 3) & 0x70);
        *(uint4*)(base + 1024 + sw) = *(const uint4*)(qbase + (size_t)r * 128 + cb);
    }
    asm volatile("fence.proxy.async.shared::cta;" ::: "memory");

    auto issueKV = [&](int ci) {
        int st = ci % 3;
        int s0 = ci * 64;
        #pragma unroll
        for (int i = 0; i < 4; i++) {
            int idx = tid + i * 128;
            int r = idx >> 3, cb = (idx & 7) * 16;
            uint32_t off = (uint32_t)(r * 128 + cb);
            uint32_t sw = off ^ ((off >> 3) & 0x70);
            bool pk = (s0 + r) < SQ;
            const char* gk = pk ? (kbase + (size_t)(s0 + r) * 128 + cb) : kbase;
            cpa16(sK + st * 8192 + sw, gk, pk);
            const char* gv = vtbase + (size_t)r * (SQP * 2) + (size_t)s0 * 2 + cb;
            cpa16(sV + st * 8192 + sw, gv, true);
        }
        cp_commit();
    };

    const uint32_t lead = (warp == 0) ? elect1() : 0;
    const uint32_t idesc = (1u << 4) | (1u << 7) | (1u << 10) | (8u << 17) | (8u << 24);

    issueKV(0);
    issueKV(1);

    float rsum = 0.0f;
    const uint64_t qd = mk_desc(sQ);
    const uint64_t pd = mk_desc(sP);

    for (int ci = 0; ci < NCH; ci++) {
        int st = ci % 3;
        int s0 = ci * 64;
        if (ci + 1 < NCH) cp_wait<1>(); else cp_wait<0>();
        __syncthreads();

        if (warp == 0 && lead) {
            uint64_t kd = mk_desc(sK + st * 8192);
            #pragma unroll
            for (int stp = 0; stp < 4; stp++)
                tg_mma_f16_ss(tmem, qd + stp * 2, kd + stp * 2, idesc, stp > 0);
            tg_commit(sb + 8);
        }
        mbar_wait(sb + 8, ci & 1);
        TG_FENCE_AFTER();

        if (ci + 2 < NCH) issueKV(ci + 2);

        uint32_t sr[32], sr2[32];
        tg_ld32(sr, tmem);
        tg_ld32(sr2, tmem + 32);
        TG_WAIT_LD();
        uint32_t pk[32];
        #pragma unroll
        for (int j = 0; j < 16; j++) {
            float e0 = (s0 + 2*j     < SQ) ? __expf(__uint_as_float(sr[2*j]))     : 0.0f;
            float e1 = (s0 + 2*j + 1 < SQ) ? __expf(__uint_as_float(sr[2*j + 1])) : 0.0f;
            rsum += e0 + e1;
            pk[j] = packbf(e0, e1);
        }
        #pragma unroll
        for (int j = 0; j < 16; j++) {
            float e0 = (s0 + 32 + 2*j     < SQ) ? __expf(__uint_as_float(sr2[2*j]))     : 0.0f;
            float e1 = (s0 + 32 + 2*j + 1 < SQ) ? __expf(__uint_as_float(sr2[2*j + 1])) : 0.0f;
            rsum += e0 + e1;
            pk[16 + j] = packbf(e0, e1);
        }
        #pragma unroll
        for (int cbk = 0; cbk < 8; cbk++) {
            uint32_t off = (uint32_t)(tid * 128 + cbk * 16);
            uint32_t sw = off ^ ((off >> 3) & 0x70);
            *(uint4*)(base + (sP - sb) + sw) =
                make_uint4(pk[4*cbk], pk[4*cbk+1], pk[4*cbk+2], pk[4*cbk+3]);
        }
        asm volatile("fence.proxy.async.shared::cta;" ::: "memory");
        __syncthreads();

        if (warp == 0 && lead) {
            uint64_t vd = mk_desc(sV + st * 8192);
            #pragma unroll
            for (int stp = 0; stp < 4; stp++)
                tg_mma_f16_ss(tmem + 64, pd + stp * 2, vd + stp * 2, idesc,
                              (ci > 0) || (stp > 0));
            if (ci == NCH - 1) tg_commit(sb + 16);
        }
    }

    mbar_wait(sb + 16, 0);
    TG_FENCE_AFTER();

    uint32_t orr[32], orr2[32];
    tg_ld32(orr, tmem + 64);
    tg_ld32(orr2, tmem + 96);
    TG_WAIT_LD();
    float inv = 1.0f / rsum;
    uint32_t po[32];
    #pragma unroll
    for (int j = 0; j < 16; j++)
        po[j] = packbf(__uint_as_float(orr[2*j]) * inv, __uint_as_float(orr[2*j+1]) * inv);
    #pragma unroll
    for (int j = 0; j < 16; j++)
        po[16+j] = packbf(__uint_as_float(orr2[2*j]) * inv, __uint_as_float(orr2[2*j+1]) * inv);
    uint4* orow = (uint4*)(O + (size_t)(b * NQ + q0 + tid) * CQ + h * HDQ);
    #pragma unroll
    for (int q = 0; q < 8; q++)
        orow[q] = make_uint4(po[4*q], po[4*q+1], po[4*q+2], po[4*q+3]);

    __syncthreads();
    if (warp == 0) TG_DEALLOC(tmem, 128);
#else
    // ---- mma.sync fallback: two sequential 64-row subtiles, V from Vt ----
    extern __shared__ bf16 fsm[];
    bf16* sQs = fsm;
    bf16* sKb = fsm + 4608;
    bf16* sVb = sKb + 3 * 4608;
    const int tid = threadIdx.x, lane = tid & 31, warp = tid >> 5;
    const int h = blockIdx.y, b = blockIdx.z;
    const bf16* kbase = K + (size_t)(b * HQ + h) * SQ * HDQ;
    const bf16* vtbase = Vt + (size_t)(b * HQ + h) * HDQ * SQP;

    for (int sub = 0; sub < 2; sub++) {
        const int q0 = blockIdx.x * 128 + sub * 64;
        const bf16* qbase = Q + ((size_t)(b * HQ + h) * SQ + IQ + q0) * HDQ;

        #pragma unroll
        for (int i = 0; i < 4; i++) {
            int chunk = tid + i * 128;
            int r = chunk >> 3, c = (chunk & 7) * 8;
            *(uint4*)(sQs + r * 72 + c) = *(const uint4*)(qbase + (size_t)r * HDQ + c);
        }

        auto issueKV = [&](int ci) {
            int s0 = ci * 64;
            int bs = ci % 3;
            #pragma unroll
            for (int i = 0; i < 4; i++) {
                int chunk = tid + i * 128;
                int r = chunk >> 3, c = (chunk & 7) * 8;
                bool p = (s0 + r) < SQ;
                const bf16* gk = p ? (kbase + (size_t)(s0 + r) * HDQ + c) : kbase;
                cpa16(smem_u32(sKb + bs * 4608 + r * 72 + c), gk, p);
                const bf16* gv = vtbase + (size_t)r * SQP + s0 + c;
                cpa16(smem_u32(sVb + bs * 4608 + r * 72 + c), gv, true);
            }
        };

        float oacc[8][4];
        #pragma unroll
        for (int t = 0; t < 8; t++)
            #pragma unroll
            for (int j = 0; j < 4; j++) oacc[t][j] = 0.0f;
        float rmax[2] = {-1e30f, -1e30f}, rsum[2] = {0.0f, 0.0f};

        const uint32_t sQ0 = smem_u32(sQs);

        issueKV(0); cp_commit();
        issueKV(1); cp_commit();

        for (int ci = 0; ci < NCH; ci++) {
            int s0 = ci * 64;
            if (ci + 1 < NCH) cp_wait<1>(); else cp_wait<0>();
            __syncthreads();
            if (ci + 2 < NCH) issueKV(ci + 2);
            cp_commit();

            const uint32_t sK0 = smem_u32(sKb + (ci % 3) * 4608);
            const uint32_t sV0 = smem_u32(sVb + (ci % 3) * 4608);

            float sc[8][4];
            #pragma unroll
            for (int t = 0; t < 8; t++)
                #pragma unroll
                for (int j = 0; j < 4; j++) sc[t][j] = 0.0f;

            #pragma unroll
            for (int kk = 0; kk < 4; kk++) {
                uint32_t af[4];
                {
                    int row = warp * 16 + (lane & 15);
                    int col = kk * 16 + ((lane >> 4) << 3);
                    ldm4(af, sQ0 + (uint32_t)((row * 72 + col) * 2));
                }
                #pragma unroll
                for (int ib = 0; ib < 4; ib++) {
                    uint32_t r4[4];
                    int g = lane >> 3;
                    int row = ib * 16 + ((g >> 1) << 3) + (lane & 7);
                    int col = kk * 16 + ((g & 1) << 3);
                    ldm4(r4, sK0 + (uint32_t)((row * 72 + col) * 2));
                    uint32_t b0[2] = {r4[0], r4[1]}, b1[2] = {r4[2], r4[3]};
                    mma_bf16(sc[2 * ib], af, b0);
                    mma_bf16(sc[2 * ib + 1], af, b1);
                }
            }

            float cmax[2] = {-1e30f, -1e30f};
            #pragma unroll
            for (int t = 0; t < 8; t++)
                #pragma unroll
                for (int j = 0; j < 4; j++) {
                    int col = s0 + t * 8 + ((lane & 3) << 1) + (j & 1);
                    if (col >= SQ) sc[t][j] = -1e30f;
                    int rr = j >> 1;
                    cmax[rr] = fmaxf(cmax[rr], sc[t][j]);
                }
            #pragma unroll
            for (int rr = 0; rr < 2; rr++) {
                cmax[rr] = fmaxf(cmax[rr], __shfl_xor_sync(0xffffffffu, cmax[rr], 1));
                cmax[rr] = fmaxf(cmax[rr], __shfl_xor_sync(0xffffffffu, cmax[rr], 2));
            }
            float corr[2];
            #pragma unroll
            for (int rr = 0; rr < 2; rr++) {
                float nm = fmaxf(rmax[rr], cmax[rr]);
                corr[rr] = __expf(rmax[rr] - nm);
                rmax[rr] = nm;
            }
            float psum[2] = {0.0f, 0.0f};
            #pragma unroll
            for (int t = 0; t < 8; t++)
                #pragma unroll
                for (int j = 0; j < 4; j++) {
                    int rr = j >> 1;
                    float p = __expf(sc[t][j] - rmax[rr]);
                    sc[t][j] = p;
                    psum[rr] += p;
                }
            #pragma unroll
            for (int rr = 0; rr < 2; rr++) {
                psum[rr] += __shfl_xor_sync(0xffffffffu, psum[rr], 1);
                psum[rr] += __shfl_xor_sync(0xffffffffu, psum[rr], 2);
                rsum[rr] = rsum[rr] * corr[rr] + psum[rr];
            }
            #pragma unroll
            for (int t = 0; t < 8; t++)
                #pragma unroll
                for (int j = 0; j < 4; j++) oacc[t][j] *= corr[j >> 1];

            #pragma unroll
            for (int kk = 0; kk < 4; kk++) {
                uint32_t ap[4];
                ap[0] = packbf(sc[2 * kk][0], sc[2 * kk][1]);
                ap[1] = packbf(sc[2 * kk][2], sc[2 * kk][3]);
                ap[2] = packbf(sc[2 * kk + 1][0], sc[2 * kk + 1][1]);
                ap[3] = packbf(sc[2 * kk + 1][2], sc[2 * kk + 1][3]);
                #pragma unroll
                for (int ib = 0; ib < 4; ib++) {
                    uint32_t r4[4];
                    int g = lane >> 3;
                    int row = ib * 16 + ((g >> 1) << 3) + (lane & 7);
                    int col = kk * 16 + ((g & 1) << 3);
                    ldm4(r4, sV0 + (uint32_t)((row * 72 + col) * 2));
                    uint32_t b0[2] = {r4[0], r4[1]}, b1[2] = {r4[2], r4[3]};
                    mma_bf16(oacc[2 * ib], ap, b0);
                    mma_bf16(oacc[2 * ib + 1], ap, b1);
                }
            }
        }

        #pragma unroll
        for (int t = 0; t < 8; t++)
            #pragma unroll
            for (int j = 0; j < 4; j++) {
                int r = q0 + warp * 16 + (lane >> 2) + ((j >> 1) << 3);
                int c = h * HDQ + t * 8 + ((lane & 3) << 1) + (j & 1);
                O[(size_t)(b * NQ + r) * CQ + c] = __float2bfloat16(oacc[t][j] / rsum[j >> 1]);
            }
        __syncthreads();
    }
#endif
}

// ---------------- launch ----------------
extern "C" void kernel_launch(void* const* d_in, const int* in_sizes, int n_in,
                              void* d_out, int out_size) {
    const float* x    = (const float*)d_in[0];
    const float* ins  = (const float*)d_in[1];
    const float* n1w  = (const float*)d_in[2];
    const float* n1b  = (const float*)d_in[3];
    const float* qkvw = (const float*)d_in[4];
    const float* qb   = (const float*)d_in[5];
    const float* vb   = (const float*)d_in[6];
    const float* pw   = (const float*)d_in[7];
    const float* pb   = (const float*)d_in[8];
    const float* g1   = (const float*)d_in[9];
    const float* g2   = (const float*)d_in[10];
    const float* n2w  = (const float*)d_in[11];
    const float* n2b  = (const float*)d_in[12];
    const float* f1w  = (const float*)d_in[13];
    const float* f1b  = (const float*)d_in[14];
    const float* f2w  = (const float*)d_in[15];
    const float* f2bv = (const float*)d_in[16];
    const float* p1w  = (const float*)d_in[17];
    const float* p1b  = (const float*)d_in[18];
    const float* p2w  = (const float*)d_in[19];
    const float* p2b  = (const float*)d_in[20];
    const float* gate = (const float*)d_in[21];
    const float* ilw  = (const float*)d_in[22];
    const float* ilb  = (const float*)d_in[23];
    const float* l1w  = (const float*)d_in[24];
    const float* l1b  = (const float*)d_in[25];
    const float* l2w  = (const float*)d_in[26];
    const float* l2b  = (const float*)d_in[27];
    float* out = (float*)d_out;

    bf16 *w_qkv, *w_proj, *w_fc1, *w_fc2, *w_l1, *w_l2;
    bf16 *insln, *hir, *cat, *qB, *kB, *vB, *obuf, *ybuf, *h1;
    float *x1, *qkvbias, *fb1c, *cb;
    cudaGetSymbolAddress((void**)&w_qkv,  g_wqkv);
    cudaGetSymbolAddress((void**)&w_proj, g_wproj);
    cudaGetSymbolAddress((void**)&w_fc1,  g_wfc1);
    cudaGetSymbolAddress((void**)&w_fc2,  g_wfc2);
    cudaGetSymbolAddress((void**)&w_l1,   g_wl1);
    cudaGetSymbolAddress((void**)&w_l2,   g_wl2);
    cudaGetSymbolAddress((void**)&insln,  g_insln);
    cudaGetSymbolAddress((void**)&hir,    g_hir);
    cudaGetSymbolAddress((void**)&cat,    g_cat);
    cudaGetSymbolAddress((void**)&qB,     g_qbuf);
    cudaGetSymbolAddress((void**)&kB,     g_kbuf);
    cudaGetSymbolAddress((void**)&vB,     g_vbuf);
    cudaGetSymbolAddress((void**)&obuf,   g_obuf);
    cudaGetSymbolAddress((void**)&ybuf,   g_ybuf);
    cudaGetSymbolAddress((void**)&h1,     g_h1);
    cudaGetSymbolAddress((void**)&x1,     g_x1);
    cudaGetSymbolAddress((void**)&qkvbias, g_qkvbias);
    cudaGetSymbolAddress((void**)&fb1c,   g_fb1c);
    cudaGetSymbolAddress((void**)&cb,     g_cb);

    cudaFuncSetAttribute(big_gemm_kernel<0>, cudaFuncAttributeMaxDynamicSharedMemorySize, BG_SMEM);
    cudaFuncSetAttribute(big_gemm_kernel<1>, cudaFuncAttributeMaxDynamicSharedMemorySize, BG_SMEM);
    cudaFuncSetAttribute(big_gemm_kernel<2>, cudaFuncAttributeMaxDynamicSharedMemorySize, BG_SMEM);
    cudaFuncSetAttribute(big_gemm_kernel<3>, cudaFuncAttributeMaxDynamicSharedMemorySize, BG_SMEM);
    cudaFuncSetAttribute(big_gemm_kernel<4>, cudaFuncAttributeMaxDynamicSharedMemorySize, BG_SMEM);
    cudaFuncSetAttribute(flash_kernel, cudaFuncAttributeMaxDynamicSharedMemorySize, FL_SMEM);

    // 1) fused front-end
    {
        MegaArgs a;
        a.qkvw = qkvw; a.pw = pw; a.l1w = l1w; a.l2w = l2w;
        a.f1w = f1w; a.p1w = p1w; a.f2w = f2w; a.p2w = p2w;
        a.qb = qb; a.vb = vb; a.f1b = f1b; a.p1b = p1b;
        a.f2b = f2bv; a.p2b = p2b; a.g2 = g2; a.gate = gate;
        a.wqkv = w_qkv; a.wproj = w_proj; a.wl1 = w_l1; a.wl2 = w_l2;
        a.wfc1 = w_fc1; a.wfc2 = w_fc2;
        a.qkvbias = qkvbias; a.fb1c = fb1c; a.cb = cb;
        a.ins = ins; a.ilw = ilw; a.ilb = ilb;
        a.x = x; a.n1w = n1w; a.n1b = n1b;
        a.insln = insln; a.cat = cat;
        mega_pre_kernel<<<MEGA_BLOCKS, 256>>>(a);
    }

    // 2) instruct l1 (gelu)
    {
        EpiParams ep; ep.bias = l1b; ep.outb = hir;
        big_gemm_kernel<0><<<dim3(CQ / 128, (BQ * IQ + 127) / 128), 256, BG_SMEM>>>(
            insln, w_l1, BQ * IQ, CQ, IDQ, ep);
    }
    // 3) instruct l2 -> cat rows [0, I)
    {
        EpiParams ep; ep.bias = l2b; ep.outb = cat;
        big_gemm_kernel<1><<<dim3(CQ / 128, (BQ * IQ + 127) / 128), 256, BG_SMEM>>>(
            hir, w_l2, BQ * IQ, CQ, CQ, ep);
    }

    // 4) qkv projection (v written transposed)
    {
        EpiParams ep; ep.bias = qkvbias; ep.q = qB; ep.k = kB; ep.v = vB;
        big_gemm_kernel<2><<<dim3(3 * CQ / 128, (BQ * SQ + 127) / 128), 256, BG_SMEM>>>(
            cat, w_qkv, BQ * SQ, 3 * CQ, CQ, ep);
    }

    // 5) attention (tcgen05 flash)
    flash_kernel<<<dim3(NQ / 128, HQ, BQ), 128, FL_SMEM>>>(qB, kB, vB, obuf);

    // 6) proj + LayerScale residual -> x1
    {
        EpiParams ep; ep.bias = pb; ep.outf = x1; ep.resid = x; ep.gvec = g1;
        big_gemm_kernel<3><<<dim3(CQ / 128, BQ * NQ / 128), 256, BG_SMEM>>>(
            obuf, w_proj, BQ * NQ, CQ, CQ, ep);
    }

    // 7) y = LN(x1)
    ln_kernel<<<BQ * NQ, 256>>>(x1, n2w, n2b, ybuf, CQ);

    // 8) combined mlp up: h1 = gelu(y @ [fc1;pfc1]^T + [f1b;p1b])
    {
        EpiParams ep; ep.bias = fb1c; ep.outb = h1;
        big_gemm_kernel<0><<<dim3(2 * HIDQ / 128, BQ * NQ / 128), 256, BG_SMEM>>>(
            ybuf, w_fc1, BQ * NQ, 2 * HIDQ, CQ, ep);
    }
    // 9) combined mlp down: out = x1 + h1 @ [g2*fc2 | gate*pfc2]^T + cb
    {
        EpiParams ep; ep.bias = cb; ep.outf = out; ep.resid = x1;
        big_gemm_kernel<4><<<dim3(CQ / 128, BQ * NQ / 128), 256, BG_SMEM>>>(
            h1, w_fc2, BQ * NQ, CQ, 2 * HIDQ, ep);
    }
}